// round 11
// baseline (speedup 1.0000x reference)
#include <cuda_runtime.h>
#include <cuda_fp16.h>
#include <cstdint>
#include <math.h>

#define Bn 16
#define Nn 3136
#define Cc 512
#define Hpix 56
#define HEADS 8
#define Dd 64
#define AG 49
#define QKV 1536

// ---------------- scratch (device globals; no allocation allowed) ----------------
__device__ __half g_qkvh[(size_t)Bn * Nn * QKV];       // fp16: q[0,512) k[512,1024) v[1024,1536)
__device__ float g_agent[(size_t)Bn * AG * Cc];        // (b,a,c)
__device__ float g_bias_ak[(size_t)HEADS * AG * Nn + 128]; // (h,a,n) +pad for cp.async tail
__device__ float g_bias_qa[(size_t)HEADS * Nn * AG];   // (h,n,a)
__device__ float g_agentv[(size_t)Bn * HEADS * AG * Dd];
__device__ __half g_xh[(size_t)Bn * Nn * Cc];          // x in fp16
__device__ __half g_acch[(size_t)Bn * Nn * Cc];        // attn out + dwc (fp16)
// transposed fp16 weights: [qT|kT|vT] rows 0..1535, projT rows 1536..2047; K-major K=512
__device__ __half g_wTh[(size_t)2048 * 512];
#define WT_PROJ (1536 * 512)

#define MMA16816(acc, a0, a1, a2, a3, b0, b1)                                   \
    asm volatile(                                                               \
        "mma.sync.aligned.m16n8k16.row.col.f32.f16.f16.f32 "                    \
        "{%0,%1,%2,%3}, {%4,%5,%6,%7}, {%8,%9}, {%0,%1,%2,%3};"                 \
        : "+f"(acc[0]), "+f"(acc[1]), "+f"(acc[2]), "+f"(acc[3])                \
        : "r"(a0), "r"(a1), "r"(a2), "r"(a3), "r"(b0), "r"(b1))

#define LDSM_X4(r0, r1, r2, r3, addr)                                           \
    asm volatile("ldmatrix.sync.aligned.m8n8.x4.shared.b16 {%0,%1,%2,%3}, [%4];" \
                 : "=r"(r0), "=r"(r1), "=r"(r2), "=r"(r3) : "r"(addr))

#define CP_ASYNC16(dst, src)                                                    \
    asm volatile("cp.async.cg.shared.global [%0], [%1], 16;\n" :: "r"(dst), "l"(src))

// ---------------- fp16 tensor-core GEMM: C = A[M,K] @ Bt[Nc,K]^T (+bias) ----------
// BM=BN=128 BK=64, 8 warps, 2-stage cp.async, 3 CTAs/SM.
#define GAS 72
#define GBUF (128 * GAS)
#define GSTAGES 2
#define GT_SMEM (GSTAGES * 2 * GBUF * 2)   // 73728 bytes

__global__ __launch_bounds__(256, 3) void gemm_h(
    const __half* __restrict__ A, const __half* __restrict__ Bt,
    float* __restrict__ Cout, __half* __restrict__ CoutH,
    int M, int K, int Nc, const float* __restrict__ bias)
{
    extern __shared__ __half smh[];
    __half* smA = smh;
    __half* smB = smh + GSTAGES * GBUF;
    const int tid = threadIdx.x;
    const int wid = tid >> 5, lane = tid & 31;
    const int wm = wid & 3, wn = wid >> 2;
    const int g = lane >> 2, cq = lane & 3;
    const int bm = blockIdx.y * 128, bn = blockIdx.x * 128;

    const uint32_t smA_u = (uint32_t)__cvta_generic_to_shared(smA);
    const uint32_t smB_u = (uint32_t)__cvta_generic_to_shared(smB);
    const uint32_t aOff = (wm * 32 + (lane & 15)) * GAS * 2 + (lane >> 4) * 16;
    const uint32_t bOff = (wn * 64 + (lane & 15)) * GAS * 2 + (lane >> 4) * 16;

    float acc[2][8][4];
#pragma unroll
    for (int i = 0; i < 2; i++)
#pragma unroll
        for (int j = 0; j < 8; j++)
#pragma unroll
            for (int t = 0; t < 4; t++) acc[i][j][t] = 0.f;

    auto loadAB = [&](int s, int kc) {
        const __half* ga = A + (size_t)bm * K + kc * 64;
        const __half* gb = Bt + (size_t)bn * K + kc * 64;
        __half* da = smA + s * GBUF;
        __half* db = smB + s * GBUF;
#pragma unroll
        for (int i = 0; i < 4; i++) {
            int idx = i * 256 + tid;
            int row = idx >> 3, seg = idx & 7;
            uint32_t pa = (uint32_t)__cvta_generic_to_shared(da + row * GAS + seg * 8);
            uint32_t pb = (uint32_t)__cvta_generic_to_shared(db + row * GAS + seg * 8);
            CP_ASYNC16(pa, ga + (size_t)row * K + seg * 8);
            CP_ASYNC16(pb, gb + (size_t)row * K + seg * 8);
        }
        asm volatile("cp.async.commit_group;\n");
    };

    const int KT = K / 64;   // 8
    loadAB(0, 0);
    loadAB(1, 1);

    for (int c = 0; c < KT; c++) {
        int s = c & 1;
        if (c + 1 < KT) asm volatile("cp.async.wait_group 1;\n");
        else            asm volatile("cp.async.wait_group 0;\n");
        __syncthreads();
        const uint32_t aP = smA_u + s * (GBUF * 2) + aOff;
        const uint32_t bP = smB_u + s * (GBUF * 2) + bOff;
#pragma unroll
        for (int ks = 0; ks < 4; ks++) {
            const uint32_t kb = ks * 32;
            uint32_t a[2][4];
            LDSM_X4(a[0][0], a[0][1], a[0][2], a[0][3], aP + kb);
            LDSM_X4(a[1][0], a[1][1], a[1][2], a[1][3], aP + 16 * GAS * 2 + kb);
#pragma unroll
            for (int jj = 0; jj < 4; jj++) {
                uint32_t rb0, rb1, rb2, rb3;
                LDSM_X4(rb0, rb1, rb2, rb3, bP + jj * (16 * GAS * 2) + kb);
#pragma unroll
                for (int i = 0; i < 2; i++) {
                    MMA16816(acc[i][2 * jj],     a[i][0], a[i][1], a[i][2], a[i][3], rb0, rb2);
                    MMA16816(acc[i][2 * jj + 1], a[i][0], a[i][1], a[i][2], a[i][3], rb1, rb3);
                }
            }
        }
        __syncthreads();
        if (c + 2 < KT) loadAB(s, c + 2);
    }

#pragma unroll
    for (int j = 0; j < 8; j++) {
        int col = bn + wn * 64 + j * 8 + 2 * cq;
        float bx = 0.f, by = 0.f;
        if (bias) { bx = bias[col]; by = bias[col + 1]; }
#pragma unroll
        for (int i = 0; i < 2; i++) {
            int r0 = bm + wm * 32 + i * 16 + g;
            if (CoutH) {
                __half2 h0 = __floats2half2_rn(acc[i][j][0] + bx, acc[i][j][1] + by);
                __half2 h1 = __floats2half2_rn(acc[i][j][2] + bx, acc[i][j][3] + by);
                *(__half2*)&CoutH[(size_t)r0 * Nc + col] = h0;
                *(__half2*)&CoutH[(size_t)(r0 + 8) * Nc + col] = h1;
            } else {
                *(float2*)&Cout[(size_t)r0 * Nc + col] =
                    make_float2(acc[i][j][0] + bx, acc[i][j][1] + by);
                *(float2*)&Cout[(size_t)(r0 + 8) * Nc + col] =
                    make_float2(acc[i][j][2] + bx, acc[i][j][3] + by);
            }
        }
    }
}

// ---------------- merged weight transpose (q|kv|proj) -> fp16 K-major -------------
__global__ __launch_bounds__(256) void wtrans_all(
    const float* __restrict__ qw, const float* __restrict__ kvw,
    const float* __restrict__ pw, __half* __restrict__ Wt)
{
    __shared__ float t[32][33];
    int n0 = blockIdx.x * 32, k0 = blockIdx.y * 32;
    const float* W;
    int Nc, col0;
    if (n0 < 512)       { W = qw;  Nc = 512;  col0 = n0; }
    else if (n0 < 1536) { W = kvw; Nc = 1024; col0 = n0 - 512; }
    else                { W = pw;  Nc = 512;  col0 = n0 - 1536; }
    int tx = threadIdx.x & 31, ty = threadIdx.x >> 5;
#pragma unroll
    for (int i = 0; i < 32; i += 8)
        t[ty + i][tx] = W[(size_t)(k0 + ty + i) * Nc + col0 + tx];
    __syncthreads();
#pragma unroll
    for (int i = 0; i < 32; i += 8)
        Wt[(size_t)(n0 + ty + i) * 512 + k0 + tx] = __float2half(t[tx][ty + i]);
}

// ---------------- fp32 -> fp16 cast ----------------
__global__ __launch_bounds__(256) void xconv_kernel(
    const float* __restrict__ src, __half* __restrict__ dst)
{
    size_t i = (size_t)blockIdx.x * 256 + threadIdx.x;
    float4 v0 = ((const float4*)src)[2 * i];
    float4 v1 = ((const float4*)src)[2 * i + 1];
    __half2 h0 = __floats2half2_rn(v0.x, v0.y);
    __half2 h1 = __floats2half2_rn(v0.z, v0.w);
    __half2 h2 = __floats2half2_rn(v1.x, v1.y);
    __half2 h3 = __floats2half2_rn(v1.z, v1.w);
    uint4 o;
    o.x = *(uint32_t*)&h0;
    o.y = *(uint32_t*)&h1;
    o.z = *(uint32_t*)&h2;
    o.w = *(uint32_t*)&h3;
    ((uint4*)dst)[i] = o;
}

// ---------------- 8x8 mean pool on fp16 q: agent[b,a,c] ----------------
__global__ __launch_bounds__(256) void pool_kernel()
{
    int idx = blockIdx.x * 256 + threadIdx.x;
    int c = idx % Cc;
    int ba = idx / Cc;
    int a = ba % AG;
    int b = ba / AG;
    int py = a / 7, px = a % 7;
    float s = 0.f;
#pragma unroll
    for (int dy = 0; dy < 8; dy++) {
        int n_base = (py * 8 + dy) * Hpix + px * 8;
#pragma unroll
        for (int dx = 0; dx < 8; dx++)
            s += __half2float(g_qkvh[((size_t)b * Nn + n_base + dx) * QKV + c]);
    }
    g_agent[idx] = s * (1.0f / 64.0f);
}

// ---------------- bilinear 7x7 -> 56x56 (half-pixel centers, edge clamp) ----------
__device__ __forceinline__ float bilerp7(const float* __restrict__ t, int y, int x)
{
    float sy = (y + 0.5f) * 0.125f - 0.5f;
    float sx = (x + 0.5f) * 0.125f - 0.5f;
    int y0f = (int)floorf(sy);
    int x0f = (int)floorf(sx);
    float wy = sy - (float)y0f;
    float wx = sx - (float)x0f;
    int y0 = min(6, max(0, y0f));
    int y1 = min(6, max(0, y0f + 1));
    int x0 = min(6, max(0, x0f));
    int x1 = min(6, max(0, x0f + 1));
    float v00 = t[y0 * 7 + x0], v01 = t[y0 * 7 + x1];
    float v10 = t[y1 * 7 + x0], v11 = t[y1 * 7 + x1];
    float top = v00 + wx * (v01 - v00);
    float bot = v10 + wx * (v11 - v10);
    return top + wy * (bot - top);
}

__global__ __launch_bounds__(256) void biasak_kernel(
    const float* __restrict__ an, const float* __restrict__ ah, const float* __restrict__ aw)
{
    int idx = blockIdx.x * 256 + threadIdx.x;
    int n = idx % Nn;
    int haa = idx / Nn;
    int y = n / Hpix, x = n % Hpix;
    g_bias_ak[idx] = bilerp7(an + haa * 49, y, x) + ah[haa] + aw[haa];
}

__global__ __launch_bounds__(256) void biasqa_kernel(
    const float* __restrict__ na, const float* __restrict__ ha, const float* __restrict__ wa)
{
    int idx = blockIdx.x * 256 + threadIdx.x;
    int a = idx % AG;
    int hn = idx / AG;
    int n = hn % Nn;
    int h = hn / Nn;
    int y = n / Hpix, x = n % Hpix;
    int haa = h * AG + a;
    g_bias_qa[idx] = bilerp7(na + haa * 49, y, x) + ha[haa] + wa[haa];
}

// ---------------- stage 1 (flash, tensor cores, double-buffered cp.async) --------
#define FS 72
#define VS 136
#define NCH 25
#define S1_AQ 0
#define S1_KS 9216
#define S1_VS 46080
#define S1_BI 80896
#define S1_SMEM 132640

__global__ __launch_bounds__(256) void stage1_mma()
{
    extern __shared__ char sm1[];
    __half* aq = (__half*)(sm1 + S1_AQ);
    float* mrg = (float*)(sm1 + S1_KS);

    const int bh = blockIdx.x;
    const int b = bh / HEADS, h = bh % HEADS;
    const int tid = threadIdx.x;
    const int wid = tid >> 5, lane = tid & 31;
    const int wm = wid & 3, wn = wid >> 2;
    const int g = lane >> 2, cq = lane & 3;

#pragma unroll
    for (int i = 0; i < 16; i++) {
        int f = i * 256 + tid;
        int a = f >> 6, d = f & 63;
        float v = (a < AG) ? g_agent[((size_t)b * AG + a) * Cc + h * Dd + d] * 0.125f : 0.f;
        aq[a * FS + d] = __float2half(v);
    }

    auto issueKB = [&](int buf, int n0) {
        char* kdst = sm1 + S1_KS + buf * 18432;
#pragma unroll
        for (int i = 0; i < 4; i++) {
            int idx = i * 256 + tid;
            int r = idx >> 3, seg = idx & 7;
            int n = min(n0 + r, Nn - 1);
            uint32_t p = (uint32_t)__cvta_generic_to_shared(kdst + (r * FS + seg * 8) * 2);
            CP_ASYNC16(p, &g_qkvh[((size_t)(b * Nn + n)) * QKV + 512 + h * Dd + seg * 8]);
        }
        char* bdst = sm1 + S1_BI + buf * 25872;
        for (int f = tid; f < AG * 32; f += 256) {
            int a = f >> 5, seg = f & 31;
            uint32_t p = (uint32_t)__cvta_generic_to_shared(bdst + (a * 132 + seg * 4) * 4);
            CP_ASYNC16(p, &g_bias_ak[((size_t)(h * AG + a)) * Nn + n0 + seg * 4]);
        }
        asm volatile("cp.async.commit_group;\n");
    };

    __half2 vxr[8], vyr[8];
    auto loadVregs = [&](int n0) {
#pragma unroll
        for (int i = 0; i < 8; i++) {
            int idx = i * 256 + tid;
            int dp = idx & 31, np = idx >> 5;
            int na = min(n0 + 2 * np, Nn - 1);
            int nb = min(n0 + 2 * np + 1, Nn - 1);
            vxr[i] = *(const __half2*)&g_qkvh[((size_t)(b * Nn + na)) * QKV + 1024 + h * Dd + dp * 2];
            vyr[i] = *(const __half2*)&g_qkvh[((size_t)(b * Nn + nb)) * QKV + 1024 + h * Dd + dp * 2];
        }
    };
    auto stsV = [&](int buf) {
        __half* vd = (__half*)(sm1 + S1_VS + buf * 17408);
#pragma unroll
        for (int i = 0; i < 8; i++) {
            int idx = i * 256 + tid;
            int dp = idx & 31, np = idx >> 5;
            *(__half2*)&vd[(2 * dp) * VS + 2 * np] = __lows2half2(vxr[i], vyr[i]);
            *(__half2*)&vd[(2 * dp + 1) * VS + 2 * np] = __highs2half2(vxr[i], vyr[i]);
        }
    };

    float m0 = -1e30f, m1 = -1e30f, l0 = 0.f, l1 = 0.f;
    float o[8][4];
#pragma unroll
    for (int j = 0; j < 8; j++)
#pragma unroll
        for (int t = 0; t < 4; t++) o[j][t] = 0.f;

    const int a0r = wm * 16 + g, a1r = a0r + 8;

    issueKB(0, 0);
    loadVregs(0);
    asm volatile("cp.async.wait_group 0;\n");
    stsV(0);
    __syncthreads();

    for (int c = 0; c < NCH; c++) {
        const int cur = c & 1, nxt = cur ^ 1;
        const int n0 = c * 128;
        if (c + 1 < NCH) {
            issueKB(nxt, (c + 1) * 128);
            loadVregs((c + 1) * 128);
        }
        const __half* ksb = (const __half*)(sm1 + S1_KS + cur * 18432);
        const __half* vsb = (const __half*)(sm1 + S1_VS + cur * 17408);
        const float* bib = (const float*)(sm1 + S1_BI + cur * 25872);

        float s[8][4];
#pragma unroll
        for (int j = 0; j < 8; j++)
#pragma unroll
            for (int t = 0; t < 4; t++) s[j][t] = 0.f;
#pragma unroll
        for (int t = 0; t < 4; t++) {
            int kk = t * 16 + 2 * cq;
            uint32_t A0 = *(const uint32_t*)&aq[(wm * 16 + g) * FS + kk];
            uint32_t A1 = *(const uint32_t*)&aq[(wm * 16 + g + 8) * FS + kk];
            uint32_t A2 = *(const uint32_t*)&aq[(wm * 16 + g) * FS + kk + 8];
            uint32_t A3 = *(const uint32_t*)&aq[(wm * 16 + g + 8) * FS + kk + 8];
#pragma unroll
            for (int j = 0; j < 8; j++) {
                int row = wn * 64 + j * 8 + g;
                uint32_t b0 = *(const uint32_t*)&ksb[row * FS + kk];
                uint32_t b1 = *(const uint32_t*)&ksb[row * FS + kk + 8];
                MMA16816(s[j], A0, A1, A2, A3, b0, b1);
            }
        }

        float cm0 = -1e30f, cm1 = -1e30f;
#pragma unroll
        for (int j = 0; j < 8; j++) {
            int nl = wn * 64 + j * 8 + 2 * cq;
            int n = n0 + nl;
            bool v0 = (n < Nn), v1 = (n + 1 < Nn);
            float ba00 = (a0r < AG) ? bib[a0r * 132 + nl] : 0.f;
            float ba01 = (a0r < AG) ? bib[a0r * 132 + nl + 1] : 0.f;
            float ba10 = (a1r < AG) ? bib[a1r * 132 + nl] : 0.f;
            float ba11 = (a1r < AG) ? bib[a1r * 132 + nl + 1] : 0.f;
            s[j][0] = v0 ? s[j][0] + ba00 : -1e30f;
            s[j][1] = v1 ? s[j][1] + ba01 : -1e30f;
            s[j][2] = v0 ? s[j][2] + ba10 : -1e30f;
            s[j][3] = v1 ? s[j][3] + ba11 : -1e30f;
            cm0 = fmaxf(cm0, fmaxf(s[j][0], s[j][1]));
            cm1 = fmaxf(cm1, fmaxf(s[j][2], s[j][3]));
        }
        cm0 = fmaxf(cm0, __shfl_xor_sync(0xffffffffu, cm0, 1));
        cm0 = fmaxf(cm0, __shfl_xor_sync(0xffffffffu, cm0, 2));
        cm1 = fmaxf(cm1, __shfl_xor_sync(0xffffffffu, cm1, 1));
        cm1 = fmaxf(cm1, __shfl_xor_sync(0xffffffffu, cm1, 2));

        float M0 = fmaxf(m0, cm0), M1 = fmaxf(m1, cm1);
        float r0 = __expf(m0 - M0), r1 = __expf(m1 - M1);
        float sum0 = 0.f, sum1 = 0.f;
#pragma unroll
        for (int j = 0; j < 8; j++) {
            s[j][0] = __expf(s[j][0] - M0);
            s[j][1] = __expf(s[j][1] - M0);
            s[j][2] = __expf(s[j][2] - M1);
            s[j][3] = __expf(s[j][3] - M1);
            sum0 += s[j][0] + s[j][1];
            sum1 += s[j][2] + s[j][3];
        }
        sum0 += __shfl_xor_sync(0xffffffffu, sum0, 1);
        sum0 += __shfl_xor_sync(0xffffffffu, sum0, 2);
        sum1 += __shfl_xor_sync(0xffffffffu, sum1, 1);
        sum1 += __shfl_xor_sync(0xffffffffu, sum1, 2);
        l0 = l0 * r0 + sum0;
        l1 = l1 * r1 + sum1;
        m0 = M0;
        m1 = M1;
#pragma unroll
        for (int j = 0; j < 8; j++) {
            o[j][0] *= r0; o[j][1] *= r0;
            o[j][2] *= r1; o[j][3] *= r1;
        }

        uint32_t pa[4][4];
#pragma unroll
        for (int t = 0; t < 4; t++) {
            __half2 h0 = __floats2half2_rn(s[2 * t][0], s[2 * t][1]);
            __half2 h1 = __floats2half2_rn(s[2 * t][2], s[2 * t][3]);
            __half2 h2 = __floats2half2_rn(s[2 * t + 1][0], s[2 * t + 1][1]);
            __half2 h3 = __floats2half2_rn(s[2 * t + 1][2], s[2 * t + 1][3]);
            pa[t][0] = *(uint32_t*)&h0;
            pa[t][1] = *(uint32_t*)&h1;
            pa[t][2] = *(uint32_t*)&h2;
            pa[t][3] = *(uint32_t*)&h3;
        }

#pragma unroll
        for (int t = 0; t < 4; t++) {
            int kk = wn * 64 + t * 16 + 2 * cq;
#pragma unroll
            for (int j = 0; j < 8; j++) {
                uint32_t b0 = *(const uint32_t*)&vsb[(j * 8 + g) * VS + kk];
                uint32_t b1 = *(const uint32_t*)&vsb[(j * 8 + g) * VS + kk + 8];
                MMA16816(o[j], pa[t][0], pa[t][1], pa[t][2], pa[t][3], b0, b1);
            }
        }

        if (c + 1 < NCH) {
            asm volatile("cp.async.wait_group 0;\n");
            stsV(nxt);
            __syncthreads();
        }
    }

    __syncthreads();
    float* p = mrg + ((size_t)(wm * 32 + lane)) * 36;
    if (wn == 1) {
#pragma unroll
        for (int j = 0; j < 8; j++) {
            p[4 * j] = o[j][0]; p[4 * j + 1] = o[j][1];
            p[4 * j + 2] = o[j][2]; p[4 * j + 3] = o[j][3];
        }
        p[32] = m0; p[33] = m1; p[34] = l0; p[35] = l1;
    }
    __syncthreads();
    if (wn == 0) {
        float pm0 = p[32], pm1 = p[33], pl0 = p[34], pl1 = p[35];
        float M0 = fmaxf(m0, pm0), M1 = fmaxf(m1, pm1);
        float ra0 = __expf(m0 - M0), rb0 = __expf(pm0 - M0);
        float ra1 = __expf(m1 - M1), rb1 = __expf(pm1 - M1);
        float i0 = 1.0f / (l0 * ra0 + pl0 * rb0);
        float i1 = 1.0f / (l1 * ra1 + pl1 * rb1);
#pragma unroll
        for (int j = 0; j < 8; j++) {
            int d = j * 8 + 2 * cq;
            if (a0r < AG) {
                float2 v = make_float2((o[j][0] * ra0 + p[4 * j] * rb0) * i0,
                                       (o[j][1] * ra0 + p[4 * j + 1] * rb0) * i0);
                *(float2*)&g_agentv[((size_t)bh * AG + a0r) * Dd + d] = v;
            }
            if (a1r < AG) {
                float2 v = make_float2((o[j][2] * ra1 + p[4 * j + 2] * rb1) * i1,
                                       (o[j][3] * ra1 + p[4 * j + 3] * rb1) * i1);
                *(float2*)&g_agentv[((size_t)bh * AG + a1r) * Dd + d] = v;
            }
        }
    }
}

// ---------------- stage 2 + fused dwc: out = softmax(q·a^T+b)@agent_v + conv(v) ---
// Dynamic smem layout (bytes):
//   qh   [128 x 72 fp16]      @ 0       (18432)
//   a4h  [ 64 x 72 fp16]      @ 18432   ( 9216)
//   avh  [ 64 x 72 fp16]      @ 27648   ( 9216)
//   vnb  [242 x 72 fp16]      @ 36864   (34848)  v neighborhood rows n0-57..n0+184
//   wsm  [9 x 64 fp32]        @ 71712   ( 2304)
//   bsm  [64 fp32]            @ 74016   (  256)
#define S2S 72
#define S2_QH 0
#define S2_A4 18432
#define S2_AV 27648
#define S2_VN 36864
#define S2_WS 71712
#define S2_BS 74016
#define S2_SMEM 74272

__global__ __launch_bounds__(256) void stage2_mma(
    const float* __restrict__ dwc_w, const float* __restrict__ dwc_b)
{
    extern __shared__ char sm2[];
    __half* qh  = (__half*)(sm2 + S2_QH);
    __half* a4h = (__half*)(sm2 + S2_A4);
    __half* avh = (__half*)(sm2 + S2_AV);
    __half* vnb = (__half*)(sm2 + S2_VN);
    float* wsm  = (float*)(sm2 + S2_WS);
    float* bsm  = (float*)(sm2 + S2_BS);

    const int bh = blockIdx.y;
    const int b = bh / HEADS, h = bh % HEADS;
    const int n0 = blockIdx.x * 128;
    const int tid = threadIdx.x;
    const int wid = tid >> 5, lane = tid & 31;
    const int g = lane >> 2, cq = lane & 3;
    const int c0 = h * Dd;
    const int nlo = n0 - 57;

    // ---- issue v-neighborhood via cp.async (242 rows x 8 segs of 16B) ----
#pragma unroll
    for (int i = 0; i < 8; i++) {
        int idx = i * 256 + tid;           // < 1936
        if (idx < 242 * 8) {
            int r = idx >> 3, seg = idx & 7;
            int n = min(max(nlo + r, 0), Nn - 1);
            uint32_t p = (uint32_t)__cvta_generic_to_shared(vnb + r * S2S + seg * 8);
            CP_ASYNC16(p, &g_qkvh[((size_t)(b * Nn + n)) * QKV + 1024 + c0 + seg * 8]);
        }
    }
    asm volatile("cp.async.commit_group;\n");

    // ---- regular smem fills ----
#pragma unroll
    for (int i = 0; i < 4; i++) {
        int idx = i * 256 + tid;
        int r = idx >> 3, seg = idx & 7;
        int n = min(n0 + r, Nn - 1);
        *(uint4*)&qh[r * S2S + seg * 8] =
            *(const uint4*)&g_qkvh[((size_t)(b * Nn + n)) * QKV + c0 + seg * 8];
    }
#pragma unroll
    for (int i = 0; i < 16; i++) {
        int idx = i * 256 + tid;
        int a = idx >> 6, d = idx & 63;
        float av = (a < AG) ? g_agent[((size_t)b * AG + a) * Cc + c0 + d] * 0.125f : 0.f;
        float vv = (a < AG) ? g_agentv[((size_t)bh * AG + a) * Dd + d] : 0.f;
        a4h[a * S2S + d] = __float2half(av);
        avh[d * S2S + a] = __float2half(vv);
    }
    // dwc weights/bias for this channel slice
    for (int i = tid; i < 9 * 64; i += 256) {
        int c = i & 63, tap = i >> 6;
        wsm[tap * 64 + c] = dwc_w[(c0 + c) * 9 + tap];
    }
    if (tid < 64) bsm[tid] = dwc_b[c0 + tid];
    __syncthreads();

    // ---- S = q @ a4^T ----
    float s[8][4];
#pragma unroll
    for (int j = 0; j < 8; j++)
#pragma unroll
        for (int t = 0; t < 4; t++) s[j][t] = 0.f;

    const __half* qa = qh + (wid * 16) * S2S;
#pragma unroll
    for (int t = 0; t < 4; t++) {
        int k = t * 16 + 2 * cq;
        uint32_t a0 = *(const uint32_t*)&qa[g * S2S + k];
        uint32_t a1 = *(const uint32_t*)&qa[(g + 8) * S2S + k];
        uint32_t a2 = *(const uint32_t*)&qa[g * S2S + k + 8];
        uint32_t a3 = *(const uint32_t*)&qa[(g + 8) * S2S + k + 8];
#pragma unroll
        for (int j = 0; j < 8; j++) {
            uint32_t b0 = *(const uint32_t*)&a4h[(j * 8 + g) * S2S + k];
            uint32_t b1 = *(const uint32_t*)&a4h[(j * 8 + g) * S2S + k + 8];
            MMA16816(s[j], a0, a1, a2, a3, b0, b1);
        }
    }

    const int r0 = n0 + wid * 16 + g;
    const int r1 = r0 + 8;
    float m0 = -1e30f, m1 = -1e30f;
#pragma unroll
    for (int j = 0; j < 8; j++) {
        int a = 8 * j + 2 * cq;
        if (a < AG) {
            float b00 = (r0 < Nn) ? g_bias_qa[((size_t)h * Nn + r0) * AG + a] : 0.f;
            float b10 = (r1 < Nn) ? g_bias_qa[((size_t)h * Nn + r1) * AG + a] : 0.f;
            s[j][0] += b00;
            s[j][2] += b10;
            if (a + 1 < AG) {
                float b01 = (r0 < Nn) ? g_bias_qa[((size_t)h * Nn + r0) * AG + a + 1] : 0.f;
                float b11 = (r1 < Nn) ? g_bias_qa[((size_t)h * Nn + r1) * AG + a + 1] : 0.f;
                s[j][1] += b01;
                s[j][3] += b11;
            } else {
                s[j][1] = -1e30f;
                s[j][3] = -1e30f;
            }
        } else {
            s[j][0] = -1e30f; s[j][1] = -1e30f;
            s[j][2] = -1e30f; s[j][3] = -1e30f;
        }
        m0 = fmaxf(m0, fmaxf(s[j][0], s[j][1]));
        m1 = fmaxf(m1, fmaxf(s[j][2], s[j][3]));
    }
    m0 = fmaxf(m0, __shfl_xor_sync(0xffffffffu, m0, 1));
    m0 = fmaxf(m0, __shfl_xor_sync(0xffffffffu, m0, 2));
    m1 = fmaxf(m1, __shfl_xor_sync(0xffffffffu, m1, 1));
    m1 = fmaxf(m1, __shfl_xor_sync(0xffffffffu, m1, 2));

    float sum0 = 0.f, sum1 = 0.f;
#pragma unroll
    for (int j = 0; j < 8; j++) {
        s[j][0] = __expf(s[j][0] - m0);
        s[j][1] = __expf(s[j][1] - m0);
        s[j][2] = __expf(s[j][2] - m1);
        s[j][3] = __expf(s[j][3] - m1);
        sum0 += s[j][0] + s[j][1];
        sum1 += s[j][2] + s[j][3];
    }
    sum0 += __shfl_xor_sync(0xffffffffu, sum0, 1);
    sum0 += __shfl_xor_sync(0xffffffffu, sum0, 2);
    sum1 += __shfl_xor_sync(0xffffffffu, sum1, 1);
    sum1 += __shfl_xor_sync(0xffffffffu, sum1, 2);
    const float inv0 = 1.0f / sum0, inv1 = 1.0f / sum1;

    uint32_t pa[4][4];
#pragma unroll
    for (int t = 0; t < 4; t++) {
        __half2 h0 = __floats2half2_rn(s[2 * t][0], s[2 * t][1]);
        __half2 h1 = __floats2half2_rn(s[2 * t][2], s[2 * t][3]);
        __half2 h2 = __floats2half2_rn(s[2 * t + 1][0], s[2 * t + 1][1]);
        __half2 h3 = __floats2half2_rn(s[2 * t + 1][2], s[2 * t + 1][3]);
        pa[t][0] = *(uint32_t*)&h0;
        pa[t][1] = *(uint32_t*)&h1;
        pa[t][2] = *(uint32_t*)&h2;
        pa[t][3] = *(uint32_t*)&h3;
    }

    float o[8][4];
#pragma unroll
    for (int j = 0; j < 8; j++)
#pragma unroll
        for (int t = 0; t < 4; t++) o[j][t] = 0.f;
#pragma unroll
    for (int t = 0; t < 4; t++) {
        int k = t * 16 + 2 * cq;
#pragma unroll
        for (int j = 0; j < 8; j++) {
            uint32_t b0 = *(const uint32_t*)&avh[(j * 8 + g) * S2S + k];
            uint32_t b1 = *(const uint32_t*)&avh[(j * 8 + g) * S2S + k + 8];
            MMA16816(o[j], pa[t][0], pa[t][1], pa[t][2], pa[t][3], b0, b1);
        }
    }

    // ---- dwc for this thread's output slots, then add + store ----
    asm volatile("cp.async.wait_group 0;\n");
    __syncthreads();

#pragma unroll
    for (int ri = 0; ri < 2; ri++) {
        int r = ri ? r1 : r0;
        if (r >= Nn) continue;
        float inv = ri ? inv1 : inv0;
        int y = r / Hpix, x = r % Hpix;
        float da[8][2];
#pragma unroll
        for (int j = 0; j < 8; j++) {
            int dl = 8 * j + 2 * cq;
            da[j][0] = bsm[dl];
            da[j][1] = bsm[dl + 1];
        }
#pragma unroll
        for (int tap = 0; tap < 9; tap++) {
            int dy = tap / 3 - 1, dx = tap % 3 - 1;
            int yy = y + dy, xx = x + dx;
            if (yy < 0 || yy >= Hpix || xx < 0 || xx >= Hpix) continue;
            int vrow = r + dy * Hpix + dx - nlo;
#pragma unroll
            for (int j = 0; j < 8; j++) {
                int dl = 8 * j + 2 * cq;
                float2 f = __half22float2(*(const __half2*)&vnb[vrow * S2S + dl]);
                da[j][0] = fmaf(f.x, wsm[tap * 64 + dl], da[j][0]);
                da[j][1] = fmaf(f.y, wsm[tap * 64 + dl + 1], da[j][1]);
            }
        }
#pragma unroll
        for (int j = 0; j < 8; j++) {
            int dl = 8 * j + 2 * cq;
            __half2 v = __floats2half2_rn(o[j][2 * ri] * inv + da[j][0],
                                          o[j][2 * ri + 1] * inv + da[j][1]);
            *(__half2*)&g_acch[((size_t)(b * Nn + r)) * Cc + c0 + dl] = v;
        }
    }
}

// ---------------- launch ----------------
extern "C" void kernel_launch(void* const* d_in, const int* in_sizes, int n_in,
                              void* d_out, int out_size)
{
    const float* x      = (const float*)d_in[0];
    const float* q_w    = (const float*)d_in[1];
    const float* kv_w   = (const float*)d_in[2];
    const float* proj_w = (const float*)d_in[3];
    const float* proj_b = (const float*)d_in[4];
    const float* dwc_w  = (const float*)d_in[5];
    const float* dwc_b  = (const float*)d_in[6];
    const float* an_b   = (const float*)d_in[7];
    const float* na_b   = (const float*)d_in[8];
    const float* ah     = (const float*)d_in[9];
    const float* aw     = (const float*)d_in[10];
    const float* ha     = (const float*)d_in[11];
    const float* wa     = (const float*)d_in[12];

    __half *qkvp, *xhp, *acchp, *wtp;
    cudaGetSymbolAddress((void**)&qkvp, g_qkvh);
    cudaGetSymbolAddress((void**)&xhp, g_xh);
    cudaGetSymbolAddress((void**)&acchp, g_acch);
    cudaGetSymbolAddress((void**)&wtp, g_wTh);

    cudaFuncSetAttribute(gemm_h, cudaFuncAttributeMaxDynamicSharedMemorySize, GT_SMEM);
    cudaFuncSetAttribute(stage1_mma, cudaFuncAttributeMaxDynamicSharedMemorySize, S1_SMEM);
    cudaFuncSetAttribute(stage2_mma, cudaFuncAttributeMaxDynamicSharedMemorySize, S2_SMEM);

    const int M = Bn * Nn;  // 50176

    wtrans_all<<<dim3(2048 / 32, 512 / 32), 256>>>(q_w, kv_w, proj_w, wtp);
    xconv_kernel<<<(int)(((size_t)M * Cc / 8) / 256), 256>>>(x, xhp);
    gemm_h<<<dim3(QKV / 128, M / 128), 256, GT_SMEM>>>(xhp, wtp, nullptr, qkvp,
                                                        M, Cc, QKV, nullptr);
    pool_kernel<<<(Bn * AG * Cc) / 256, 256>>>();
    biasak_kernel<<<(HEADS * AG * Nn) / 256, 256>>>(an_b, ah, aw);
    biasqa_kernel<<<(HEADS * Nn * AG) / 256, 256>>>(na_b, ha, wa);
    stage1_mma<<<Bn * HEADS, 256, S1_SMEM>>>();
    stage2_mma<<<dim3(25, Bn * HEADS), 256, S2_SMEM>>>(dwc_w, dwc_b);
    gemm_h<<<dim3(Cc / 128, M / 128), 256, GT_SMEM>>>(acchp, wtp + WT_PROJ, (float*)d_out,
                                                       nullptr, M, Cc, Cc, proj_b);
}

// round 12
// speedup vs baseline: 1.3695x; 1.3695x over previous
#include <cuda_runtime.h>
#include <cuda_fp16.h>
#include <cstdint>
#include <math.h>

#define Bn 16
#define Nn 3136
#define Cc 512
#define Hpix 56
#define HEADS 8
#define Dd 64
#define AG 49
#define QKV 1536

// ---------------- scratch (device globals; no allocation allowed) ----------------
__device__ __half g_qkvh[(size_t)Bn * Nn * QKV];       // fp16: q[0,512) k[512,1024) v[1024,1536)
__device__ float g_agent[(size_t)Bn * AG * Cc];        // (b,a,c)
__device__ float g_bias_ak[(size_t)HEADS * AG * Nn + 128]; // (h,a,n) +pad for cp.async tail
__device__ float g_bias_qa[(size_t)HEADS * Nn * AG];   // (h,n,a)
__device__ float g_agentv[(size_t)Bn * HEADS * AG * Dd];
__device__ __half g_xh[(size_t)Bn * Nn * Cc];          // x in fp16
__device__ __half g_acch[(size_t)Bn * Nn * Cc];        // attn out + dwc (fp16)
// transposed fp16 weights: [qT|kT|vT] rows 0..1535, projT rows 1536..2047; K-major K=512
__device__ __half g_wTh[(size_t)2048 * 512];
#define WT_PROJ (1536 * 512)

#define MMA16816(acc, a0, a1, a2, a3, b0, b1)                                   \
    asm volatile(                                                               \
        "mma.sync.aligned.m16n8k16.row.col.f32.f16.f16.f32 "                    \
        "{%0,%1,%2,%3}, {%4,%5,%6,%7}, {%8,%9}, {%0,%1,%2,%3};"                 \
        : "+f"(acc[0]), "+f"(acc[1]), "+f"(acc[2]), "+f"(acc[3])                \
        : "r"(a0), "r"(a1), "r"(a2), "r"(a3), "r"(b0), "r"(b1))

#define LDSM_X4(r0, r1, r2, r3, addr)                                           \
    asm volatile("ldmatrix.sync.aligned.m8n8.x4.shared.b16 {%0,%1,%2,%3}, [%4];" \
                 : "=r"(r0), "=r"(r1), "=r"(r2), "=r"(r3) : "r"(addr))

#define CP_ASYNC16(dst, src)                                                    \
    asm volatile("cp.async.cg.shared.global [%0], [%1], 16;\n" :: "r"(dst), "l"(src))

// ---------------- fp16 tensor-core GEMM: C = A[M,K] @ Bt[Nc,K]^T (+bias) ----------
// BM=BN=128 BK=64, 8 warps, 3-stage cp.async, 2 CTAs/SM.  (R9-verified config)
#define GAS 72
#define GBUF (128 * GAS)
#define GSTAGES 3
#define GT_SMEM (GSTAGES * 2 * GBUF * 2)   // 110592 bytes

__global__ __launch_bounds__(256, 2) void gemm_h(
    const __half* __restrict__ A, const __half* __restrict__ Bt,
    float* __restrict__ Cout, __half* __restrict__ CoutH,
    int M, int K, int Nc, const float* __restrict__ bias)
{
    extern __shared__ __half smh[];
    __half* smA = smh;
    __half* smB = smh + GSTAGES * GBUF;
    const int tid = threadIdx.x;
    const int wid = tid >> 5, lane = tid & 31;
    const int wm = wid & 3, wn = wid >> 2;
    const int g = lane >> 2, cq = lane & 3;
    const int bm = blockIdx.y * 128, bn = blockIdx.x * 128;

    const uint32_t smA_u = (uint32_t)__cvta_generic_to_shared(smA);
    const uint32_t smB_u = (uint32_t)__cvta_generic_to_shared(smB);
    const uint32_t aOff = (wm * 32 + (lane & 15)) * GAS * 2 + (lane >> 4) * 16;
    const uint32_t bOff = (wn * 64 + (lane & 15)) * GAS * 2 + (lane >> 4) * 16;

    float acc[2][8][4];
#pragma unroll
    for (int i = 0; i < 2; i++)
#pragma unroll
        for (int j = 0; j < 8; j++)
#pragma unroll
            for (int t = 0; t < 4; t++) acc[i][j][t] = 0.f;

    auto loadAB = [&](int s, int kc) {
        const __half* ga = A + (size_t)bm * K + kc * 64;
        const __half* gb = Bt + (size_t)bn * K + kc * 64;
        __half* da = smA + s * GBUF;
        __half* db = smB + s * GBUF;
#pragma unroll
        for (int i = 0; i < 4; i++) {
            int idx = i * 256 + tid;
            int row = idx >> 3, seg = idx & 7;
            uint32_t pa = (uint32_t)__cvta_generic_to_shared(da + row * GAS + seg * 8);
            uint32_t pb = (uint32_t)__cvta_generic_to_shared(db + row * GAS + seg * 8);
            CP_ASYNC16(pa, ga + (size_t)row * K + seg * 8);
            CP_ASYNC16(pb, gb + (size_t)row * K + seg * 8);
        }
        asm volatile("cp.async.commit_group;\n");
    };

    const int KT = K / 64;   // 8
    loadAB(0, 0);
    loadAB(1, 1);
    loadAB(2, 2);

    for (int c = 0; c < KT; c++) {
        int s = c % GSTAGES;
        if (c + 2 < KT)      asm volatile("cp.async.wait_group 2;\n");
        else if (c + 1 < KT) asm volatile("cp.async.wait_group 1;\n");
        else                 asm volatile("cp.async.wait_group 0;\n");
        __syncthreads();
        const uint32_t aP = smA_u + s * (GBUF * 2) + aOff;
        const uint32_t bP = smB_u + s * (GBUF * 2) + bOff;
#pragma unroll
        for (int ks = 0; ks < 4; ks++) {
            const uint32_t kb = ks * 32;
            uint32_t a[2][4];
            LDSM_X4(a[0][0], a[0][1], a[0][2], a[0][3], aP + kb);
            LDSM_X4(a[1][0], a[1][1], a[1][2], a[1][3], aP + 16 * GAS * 2 + kb);
#pragma unroll
            for (int jj = 0; jj < 4; jj++) {
                uint32_t rb0, rb1, rb2, rb3;
                LDSM_X4(rb0, rb1, rb2, rb3, bP + jj * (16 * GAS * 2) + kb);
#pragma unroll
                for (int i = 0; i < 2; i++) {
                    MMA16816(acc[i][2 * jj],     a[i][0], a[i][1], a[i][2], a[i][3], rb0, rb2);
                    MMA16816(acc[i][2 * jj + 1], a[i][0], a[i][1], a[i][2], a[i][3], rb1, rb3);
                }
            }
        }
        __syncthreads();
        if (c + GSTAGES < KT) loadAB(s, c + GSTAGES);
    }

#pragma unroll
    for (int j = 0; j < 8; j++) {
        int col = bn + wn * 64 + j * 8 + 2 * cq;
        float bx = 0.f, by = 0.f;
        if (bias) { bx = bias[col]; by = bias[col + 1]; }
#pragma unroll
        for (int i = 0; i < 2; i++) {
            int r0 = bm + wm * 32 + i * 16 + g;
            if (CoutH) {
                __half2 h0 = __floats2half2_rn(acc[i][j][0] + bx, acc[i][j][1] + by);
                __half2 h1 = __floats2half2_rn(acc[i][j][2] + bx, acc[i][j][3] + by);
                *(__half2*)&CoutH[(size_t)r0 * Nc + col] = h0;
                *(__half2*)&CoutH[(size_t)(r0 + 8) * Nc + col] = h1;
            } else {
                *(float2*)&Cout[(size_t)r0 * Nc + col] =
                    make_float2(acc[i][j][0] + bx, acc[i][j][1] + by);
                *(float2*)&Cout[(size_t)(r0 + 8) * Nc + col] =
                    make_float2(acc[i][j][2] + bx, acc[i][j][3] + by);
            }
        }
    }
}

// ---------------- merged weight transpose (q|kv|proj) -> fp16 K-major -------------
__global__ __launch_bounds__(256) void wtrans_all(
    const float* __restrict__ qw, const float* __restrict__ kvw,
    const float* __restrict__ pw, __half* __restrict__ Wt)
{
    __shared__ float t[32][33];
    int n0 = blockIdx.x * 32, k0 = blockIdx.y * 32;
    const float* W;
    int Nc, col0;
    if (n0 < 512)       { W = qw;  Nc = 512;  col0 = n0; }
    else if (n0 < 1536) { W = kvw; Nc = 1024; col0 = n0 - 512; }
    else                { W = pw;  Nc = 512;  col0 = n0 - 1536; }
    int tx = threadIdx.x & 31, ty = threadIdx.x >> 5;
#pragma unroll
    for (int i = 0; i < 32; i += 8)
        t[ty + i][tx] = W[(size_t)(k0 + ty + i) * Nc + col0 + tx];
    __syncthreads();
#pragma unroll
    for (int i = 0; i < 32; i += 8)
        Wt[(size_t)(n0 + ty + i) * 512 + k0 + tx] = __float2half(t[tx][ty + i]);
}

// ---------------- fp32 -> fp16 cast ----------------
__global__ __launch_bounds__(256) void xconv_kernel(
    const float* __restrict__ src, __half* __restrict__ dst)
{
    size_t i = (size_t)blockIdx.x * 256 + threadIdx.x;
    float4 v0 = ((const float4*)src)[2 * i];
    float4 v1 = ((const float4*)src)[2 * i + 1];
    __half2 h0 = __floats2half2_rn(v0.x, v0.y);
    __half2 h1 = __floats2half2_rn(v0.z, v0.w);
    __half2 h2 = __floats2half2_rn(v1.x, v1.y);
    __half2 h3 = __floats2half2_rn(v1.z, v1.w);
    uint4 o;
    o.x = *(uint32_t*)&h0;
    o.y = *(uint32_t*)&h1;
    o.z = *(uint32_t*)&h2;
    o.w = *(uint32_t*)&h3;
    ((uint4*)dst)[i] = o;
}

// ---------------- 8x8 mean pool on fp16 q: agent[b,a,c] ----------------
__global__ __launch_bounds__(256) void pool_kernel()
{
    int idx = blockIdx.x * 256 + threadIdx.x;
    int c = idx % Cc;
    int ba = idx / Cc;
    int a = ba % AG;
    int b = ba / AG;
    int py = a / 7, px = a % 7;
    float s = 0.f;
#pragma unroll
    for (int dy = 0; dy < 8; dy++) {
        int n_base = (py * 8 + dy) * Hpix + px * 8;
#pragma unroll
        for (int dx = 0; dx < 8; dx++)
            s += __half2float(g_qkvh[((size_t)b * Nn + n_base + dx) * QKV + c]);
    }
    g_agent[idx] = s * (1.0f / 64.0f);
}

// ---------------- bilinear 7x7 -> 56x56 (half-pixel centers, edge clamp) ----------
__device__ __forceinline__ float bilerp7(const float* __restrict__ t, int y, int x)
{
    float sy = (y + 0.5f) * 0.125f - 0.5f;
    float sx = (x + 0.5f) * 0.125f - 0.5f;
    int y0f = (int)floorf(sy);
    int x0f = (int)floorf(sx);
    float wy = sy - (float)y0f;
    float wx = sx - (float)x0f;
    int y0 = min(6, max(0, y0f));
    int y1 = min(6, max(0, y0f + 1));
    int x0 = min(6, max(0, x0f));
    int x1 = min(6, max(0, x0f + 1));
    float v00 = t[y0 * 7 + x0], v01 = t[y0 * 7 + x1];
    float v10 = t[y1 * 7 + x0], v11 = t[y1 * 7 + x1];
    float top = v00 + wx * (v01 - v00);
    float bot = v10 + wx * (v11 - v10);
    return top + wy * (bot - top);
}

__global__ __launch_bounds__(256) void biasak_kernel(
    const float* __restrict__ an, const float* __restrict__ ah, const float* __restrict__ aw)
{
    int idx = blockIdx.x * 256 + threadIdx.x;
    int n = idx % Nn;
    int haa = idx / Nn;
    int y = n / Hpix, x = n % Hpix;
    g_bias_ak[idx] = bilerp7(an + haa * 49, y, x) + ah[haa] + aw[haa];
}

__global__ __launch_bounds__(256) void biasqa_kernel(
    const float* __restrict__ na, const float* __restrict__ ha, const float* __restrict__ wa)
{
    int idx = blockIdx.x * 256 + threadIdx.x;
    int a = idx % AG;
    int hn = idx / AG;
    int n = hn % Nn;
    int h = hn / Nn;
    int y = n / Hpix, x = n % Hpix;
    int haa = h * AG + a;
    g_bias_qa[idx] = bilerp7(na + haa * 49, y, x) + ha[haa] + wa[haa];
}

// ---------------- stage 1 (flash, tensor cores, double-buffered cp.async) --------
#define FS 72
#define VS 136
#define NCH 25
#define S1_AQ 0
#define S1_KS 9216
#define S1_VS 46080
#define S1_BI 80896
#define S1_SMEM 132640

__global__ __launch_bounds__(256) void stage1_mma()
{
    extern __shared__ char sm1[];
    __half* aq = (__half*)(sm1 + S1_AQ);
    float* mrg = (float*)(sm1 + S1_KS);

    const int bh = blockIdx.x;
    const int b = bh / HEADS, h = bh % HEADS;
    const int tid = threadIdx.x;
    const int wid = tid >> 5, lane = tid & 31;
    const int wm = wid & 3, wn = wid >> 2;
    const int g = lane >> 2, cq = lane & 3;

#pragma unroll
    for (int i = 0; i < 16; i++) {
        int f = i * 256 + tid;
        int a = f >> 6, d = f & 63;
        float v = (a < AG) ? g_agent[((size_t)b * AG + a) * Cc + h * Dd + d] * 0.125f : 0.f;
        aq[a * FS + d] = __float2half(v);
    }

    auto issueKB = [&](int buf, int n0) {
        char* kdst = sm1 + S1_KS + buf * 18432;
#pragma unroll
        for (int i = 0; i < 4; i++) {
            int idx = i * 256 + tid;
            int r = idx >> 3, seg = idx & 7;
            int n = min(n0 + r, Nn - 1);
            uint32_t p = (uint32_t)__cvta_generic_to_shared(kdst + (r * FS + seg * 8) * 2);
            CP_ASYNC16(p, &g_qkvh[((size_t)(b * Nn + n)) * QKV + 512 + h * Dd + seg * 8]);
        }
        char* bdst = sm1 + S1_BI + buf * 25872;
        for (int f = tid; f < AG * 32; f += 256) {
            int a = f >> 5, seg = f & 31;
            uint32_t p = (uint32_t)__cvta_generic_to_shared(bdst + (a * 132 + seg * 4) * 4);
            CP_ASYNC16(p, &g_bias_ak[((size_t)(h * AG + a)) * Nn + n0 + seg * 4]);
        }
        asm volatile("cp.async.commit_group;\n");
    };

    __half2 vxr[8], vyr[8];
    auto loadVregs = [&](int n0) {
#pragma unroll
        for (int i = 0; i < 8; i++) {
            int idx = i * 256 + tid;
            int dp = idx & 31, np = idx >> 5;
            int na = min(n0 + 2 * np, Nn - 1);
            int nb = min(n0 + 2 * np + 1, Nn - 1);
            vxr[i] = *(const __half2*)&g_qkvh[((size_t)(b * Nn + na)) * QKV + 1024 + h * Dd + dp * 2];
            vyr[i] = *(const __half2*)&g_qkvh[((size_t)(b * Nn + nb)) * QKV + 1024 + h * Dd + dp * 2];
        }
    };
    auto stsV = [&](int buf) {
        __half* vd = (__half*)(sm1 + S1_VS + buf * 17408);
#pragma unroll
        for (int i = 0; i < 8; i++) {
            int idx = i * 256 + tid;
            int dp = idx & 31, np = idx >> 5;
            *(__half2*)&vd[(2 * dp) * VS + 2 * np] = __lows2half2(vxr[i], vyr[i]);
            *(__half2*)&vd[(2 * dp + 1) * VS + 2 * np] = __highs2half2(vxr[i], vyr[i]);
        }
    };

    float m0 = -1e30f, m1 = -1e30f, l0 = 0.f, l1 = 0.f;
    float o[8][4];
#pragma unroll
    for (int j = 0; j < 8; j++)
#pragma unroll
        for (int t = 0; t < 4; t++) o[j][t] = 0.f;

    const int a0r = wm * 16 + g, a1r = a0r + 8;

    issueKB(0, 0);
    loadVregs(0);
    asm volatile("cp.async.wait_group 0;\n");
    stsV(0);
    __syncthreads();

    for (int c = 0; c < NCH; c++) {
        const int cur = c & 1, nxt = cur ^ 1;
        const int n0 = c * 128;
        if (c + 1 < NCH) {
            issueKB(nxt, (c + 1) * 128);
            loadVregs((c + 1) * 128);
        }
        const __half* ksb = (const __half*)(sm1 + S1_KS + cur * 18432);
        const __half* vsb = (const __half*)(sm1 + S1_VS + cur * 17408);
        const float* bib = (const float*)(sm1 + S1_BI + cur * 25872);

        float s[8][4];
#pragma unroll
        for (int j = 0; j < 8; j++)
#pragma unroll
            for (int t = 0; t < 4; t++) s[j][t] = 0.f;
#pragma unroll
        for (int t = 0; t < 4; t++) {
            int kk = t * 16 + 2 * cq;
            uint32_t A0 = *(const uint32_t*)&aq[(wm * 16 + g) * FS + kk];
            uint32_t A1 = *(const uint32_t*)&aq[(wm * 16 + g + 8) * FS + kk];
            uint32_t A2 = *(const uint32_t*)&aq[(wm * 16 + g) * FS + kk + 8];
            uint32_t A3 = *(const uint32_t*)&aq[(wm * 16 + g + 8) * FS + kk + 8];
#pragma unroll
            for (int j = 0; j < 8; j++) {
                int row = wn * 64 + j * 8 + g;
                uint32_t b0 = *(const uint32_t*)&ksb[row * FS + kk];
                uint32_t b1 = *(const uint32_t*)&ksb[row * FS + kk + 8];
                MMA16816(s[j], A0, A1, A2, A3, b0, b1);
            }
        }

        float cm0 = -1e30f, cm1 = -1e30f;
#pragma unroll
        for (int j = 0; j < 8; j++) {
            int nl = wn * 64 + j * 8 + 2 * cq;
            int n = n0 + nl;
            bool v0 = (n < Nn), v1 = (n + 1 < Nn);
            float ba00 = (a0r < AG) ? bib[a0r * 132 + nl] : 0.f;
            float ba01 = (a0r < AG) ? bib[a0r * 132 + nl + 1] : 0.f;
            float ba10 = (a1r < AG) ? bib[a1r * 132 + nl] : 0.f;
            float ba11 = (a1r < AG) ? bib[a1r * 132 + nl + 1] : 0.f;
            s[j][0] = v0 ? s[j][0] + ba00 : -1e30f;
            s[j][1] = v1 ? s[j][1] + ba01 : -1e30f;
            s[j][2] = v0 ? s[j][2] + ba10 : -1e30f;
            s[j][3] = v1 ? s[j][3] + ba11 : -1e30f;
            cm0 = fmaxf(cm0, fmaxf(s[j][0], s[j][1]));
            cm1 = fmaxf(cm1, fmaxf(s[j][2], s[j][3]));
        }
        cm0 = fmaxf(cm0, __shfl_xor_sync(0xffffffffu, cm0, 1));
        cm0 = fmaxf(cm0, __shfl_xor_sync(0xffffffffu, cm0, 2));
        cm1 = fmaxf(cm1, __shfl_xor_sync(0xffffffffu, cm1, 1));
        cm1 = fmaxf(cm1, __shfl_xor_sync(0xffffffffu, cm1, 2));

        float M0 = fmaxf(m0, cm0), M1 = fmaxf(m1, cm1);
        float r0 = __expf(m0 - M0), r1 = __expf(m1 - M1);
        float sum0 = 0.f, sum1 = 0.f;
#pragma unroll
        for (int j = 0; j < 8; j++) {
            s[j][0] = __expf(s[j][0] - M0);
            s[j][1] = __expf(s[j][1] - M0);
            s[j][2] = __expf(s[j][2] - M1);
            s[j][3] = __expf(s[j][3] - M1);
            sum0 += s[j][0] + s[j][1];
            sum1 += s[j][2] + s[j][3];
        }
        sum0 += __shfl_xor_sync(0xffffffffu, sum0, 1);
        sum0 += __shfl_xor_sync(0xffffffffu, sum0, 2);
        sum1 += __shfl_xor_sync(0xffffffffu, sum1, 1);
        sum1 += __shfl_xor_sync(0xffffffffu, sum1, 2);
        l0 = l0 * r0 + sum0;
        l1 = l1 * r1 + sum1;
        m0 = M0;
        m1 = M1;
#pragma unroll
        for (int j = 0; j < 8; j++) {
            o[j][0] *= r0; o[j][1] *= r0;
            o[j][2] *= r1; o[j][3] *= r1;
        }

        uint32_t pa[4][4];
#pragma unroll
        for (int t = 0; t < 4; t++) {
            __half2 h0 = __floats2half2_rn(s[2 * t][0], s[2 * t][1]);
            __half2 h1 = __floats2half2_rn(s[2 * t][2], s[2 * t][3]);
            __half2 h2 = __floats2half2_rn(s[2 * t + 1][0], s[2 * t + 1][1]);
            __half2 h3 = __floats2half2_rn(s[2 * t + 1][2], s[2 * t + 1][3]);
            pa[t][0] = *(uint32_t*)&h0;
            pa[t][1] = *(uint32_t*)&h1;
            pa[t][2] = *(uint32_t*)&h2;
            pa[t][3] = *(uint32_t*)&h3;
        }

#pragma unroll
        for (int t = 0; t < 4; t++) {
            int kk = wn * 64 + t * 16 + 2 * cq;
#pragma unroll
            for (int j = 0; j < 8; j++) {
                uint32_t b0 = *(const uint32_t*)&vsb[(j * 8 + g) * VS + kk];
                uint32_t b1 = *(const uint32_t*)&vsb[(j * 8 + g) * VS + kk + 8];
                MMA16816(o[j], pa[t][0], pa[t][1], pa[t][2], pa[t][3], b0, b1);
            }
        }

        if (c + 1 < NCH) {
            asm volatile("cp.async.wait_group 0;\n");
            stsV(nxt);
            __syncthreads();
        }
    }

    __syncthreads();
    float* p = mrg + ((size_t)(wm * 32 + lane)) * 36;
    if (wn == 1) {
#pragma unroll
        for (int j = 0; j < 8; j++) {
            p[4 * j] = o[j][0]; p[4 * j + 1] = o[j][1];
            p[4 * j + 2] = o[j][2]; p[4 * j + 3] = o[j][3];
        }
        p[32] = m0; p[33] = m1; p[34] = l0; p[35] = l1;
    }
    __syncthreads();
    if (wn == 0) {
        float pm0 = p[32], pm1 = p[33], pl0 = p[34], pl1 = p[35];
        float M0 = fmaxf(m0, pm0), M1 = fmaxf(m1, pm1);
        float ra0 = __expf(m0 - M0), rb0 = __expf(pm0 - M0);
        float ra1 = __expf(m1 - M1), rb1 = __expf(pm1 - M1);
        float i0 = 1.0f / (l0 * ra0 + pl0 * rb0);
        float i1 = 1.0f / (l1 * ra1 + pl1 * rb1);
#pragma unroll
        for (int j = 0; j < 8; j++) {
            int d = j * 8 + 2 * cq;
            if (a0r < AG) {
                float2 v = make_float2((o[j][0] * ra0 + p[4 * j] * rb0) * i0,
                                       (o[j][1] * ra0 + p[4 * j + 1] * rb0) * i0);
                *(float2*)&g_agentv[((size_t)bh * AG + a0r) * Dd + d] = v;
            }
            if (a1r < AG) {
                float2 v = make_float2((o[j][2] * ra1 + p[4 * j + 2] * rb1) * i1,
                                       (o[j][3] * ra1 + p[4 * j + 3] * rb1) * i1);
                *(float2*)&g_agentv[((size_t)bh * AG + a1r) * Dd + d] = v;
            }
        }
    }
}

// ---------------- stage 2 + fused dwc: out = softmax(q·a^T+b)@agent_v + conv(v) ---
#define S2S 72
#define S2_QH 0
#define S2_A4 18432
#define S2_AV 27648
#define S2_VN 36864
#define S2_WS 71712
#define S2_BS 74016
#define S2_SMEM 74272

__global__ __launch_bounds__(256) void stage2_mma(
    const float* __restrict__ dwc_w, const float* __restrict__ dwc_b)
{
    extern __shared__ char sm2[];
    __half* qh  = (__half*)(sm2 + S2_QH);
    __half* a4h = (__half*)(sm2 + S2_A4);
    __half* avh = (__half*)(sm2 + S2_AV);
    __half* vnb = (__half*)(sm2 + S2_VN);
    float* wsm  = (float*)(sm2 + S2_WS);
    float* bsm  = (float*)(sm2 + S2_BS);

    const int bh = blockIdx.y;
    const int b = bh / HEADS, h = bh % HEADS;
    const int n0 = blockIdx.x * 128;
    const int tid = threadIdx.x;
    const int wid = tid >> 5, lane = tid & 31;
    const int g = lane >> 2, cq = lane & 3;
    const int c0 = h * Dd;
    const int nlo = n0 - 57;

#pragma unroll
    for (int i = 0; i < 8; i++) {
        int idx = i * 256 + tid;
        if (idx < 242 * 8) {
            int r = idx >> 3, seg = idx & 7;
            int n = min(max(nlo + r, 0), Nn - 1);
            uint32_t p = (uint32_t)__cvta_generic_to_shared(vnb + r * S2S + seg * 8);
            CP_ASYNC16(p, &g_qkvh[((size_t)(b * Nn + n)) * QKV + 1024 + c0 + seg * 8]);
        }
    }
    asm volatile("cp.async.commit_group;\n");

#pragma unroll
    for (int i = 0; i < 4; i++) {
        int idx = i * 256 + tid;
        int r = idx >> 3, seg = idx & 7;
        int n = min(n0 + r, Nn - 1);
        *(uint4*)&qh[r * S2S + seg * 8] =
            *(const uint4*)&g_qkvh[((size_t)(b * Nn + n)) * QKV + c0 + seg * 8];
    }
#pragma unroll
    for (int i = 0; i < 16; i++) {
        int idx = i * 256 + tid;
        int a = idx >> 6, d = idx & 63;
        float av = (a < AG) ? g_agent[((size_t)b * AG + a) * Cc + c0 + d] * 0.125f : 0.f;
        float vv = (a < AG) ? g_agentv[((size_t)bh * AG + a) * Dd + d] : 0.f;
        a4h[a * S2S + d] = __float2half(av);
        avh[d * S2S + a] = __float2half(vv);
    }
    for (int i = tid; i < 9 * 64; i += 256) {
        int c = i & 63, tap = i >> 6;
        wsm[tap * 64 + c] = dwc_w[(c0 + c) * 9 + tap];
    }
    if (tid < 64) bsm[tid] = dwc_b[c0 + tid];
    __syncthreads();

    float s[8][4];
#pragma unroll
    for (int j = 0; j < 8; j++)
#pragma unroll
        for (int t = 0; t < 4; t++) s[j][t] = 0.f;

    const __half* qa = qh + (wid * 16) * S2S;
#pragma unroll
    for (int t = 0; t < 4; t++) {
        int k = t * 16 + 2 * cq;
        uint32_t a0 = *(const uint32_t*)&qa[g * S2S + k];
        uint32_t a1 = *(const uint32_t*)&qa[(g + 8) * S2S + k];
        uint32_t a2 = *(const uint32_t*)&qa[g * S2S + k + 8];
        uint32_t a3 = *(const uint32_t*)&qa[(g + 8) * S2S + k + 8];
#pragma unroll
        for (int j = 0; j < 8; j++) {
            uint32_t b0 = *(const uint32_t*)&a4h[(j * 8 + g) * S2S + k];
            uint32_t b1 = *(const uint32_t*)&a4h[(j * 8 + g) * S2S + k + 8];
            MMA16816(s[j], a0, a1, a2, a3, b0, b1);
        }
    }

    const int r0 = n0 + wid * 16 + g;
    const int r1 = r0 + 8;
    float m0 = -1e30f, m1 = -1e30f;
#pragma unroll
    for (int j = 0; j < 8; j++) {
        int a = 8 * j + 2 * cq;
        if (a < AG) {
            float b00 = (r0 < Nn) ? g_bias_qa[((size_t)h * Nn + r0) * AG + a] : 0.f;
            float b10 = (r1 < Nn) ? g_bias_qa[((size_t)h * Nn + r1) * AG + a] : 0.f;
            s[j][0] += b00;
            s[j][2] += b10;
            if (a + 1 < AG) {
                float b01 = (r0 < Nn) ? g_bias_qa[((size_t)h * Nn + r0) * AG + a + 1] : 0.f;
                float b11 = (r1 < Nn) ? g_bias_qa[((size_t)h * Nn + r1) * AG + a + 1] : 0.f;
                s[j][1] += b01;
                s[j][3] += b11;
            } else {
                s[j][1] = -1e30f;
                s[j][3] = -1e30f;
            }
        } else {
            s[j][0] = -1e30f; s[j][1] = -1e30f;
            s[j][2] = -1e30f; s[j][3] = -1e30f;
        }
        m0 = fmaxf(m0, fmaxf(s[j][0], s[j][1]));
        m1 = fmaxf(m1, fmaxf(s[j][2], s[j][3]));
    }
    m0 = fmaxf(m0, __shfl_xor_sync(0xffffffffu, m0, 1));
    m0 = fmaxf(m0, __shfl_xor_sync(0xffffffffu, m0, 2));
    m1 = fmaxf(m1, __shfl_xor_sync(0xffffffffu, m1, 1));
    m1 = fmaxf(m1, __shfl_xor_sync(0xffffffffu, m1, 2));

    float sum0 = 0.f, sum1 = 0.f;
#pragma unroll
    for (int j = 0; j < 8; j++) {
        s[j][0] = __expf(s[j][0] - m0);
        s[j][1] = __expf(s[j][1] - m0);
        s[j][2] = __expf(s[j][2] - m1);
        s[j][3] = __expf(s[j][3] - m1);
        sum0 += s[j][0] + s[j][1];
        sum1 += s[j][2] + s[j][3];
    }
    sum0 += __shfl_xor_sync(0xffffffffu, sum0, 1);
    sum0 += __shfl_xor_sync(0xffffffffu, sum0, 2);
    sum1 += __shfl_xor_sync(0xffffffffu, sum1, 1);
    sum1 += __shfl_xor_sync(0xffffffffu, sum1, 2);
    const float inv0 = 1.0f / sum0, inv1 = 1.0f / sum1;

    uint32_t pa[4][4];
#pragma unroll
    for (int t = 0; t < 4; t++) {
        __half2 h0 = __floats2half2_rn(s[2 * t][0], s[2 * t][1]);
        __half2 h1 = __floats2half2_rn(s[2 * t][2], s[2 * t][3]);
        __half2 h2 = __floats2half2_rn(s[2 * t + 1][0], s[2 * t + 1][1]);
        __half2 h3 = __floats2half2_rn(s[2 * t + 1][2], s[2 * t + 1][3]);
        pa[t][0] = *(uint32_t*)&h0;
        pa[t][1] = *(uint32_t*)&h1;
        pa[t][2] = *(uint32_t*)&h2;
        pa[t][3] = *(uint32_t*)&h3;
    }

    float o[8][4];
#pragma unroll
    for (int j = 0; j < 8; j++)
#pragma unroll
        for (int t = 0; t < 4; t++) o[j][t] = 0.f;
#pragma unroll
    for (int t = 0; t < 4; t++) {
        int k = t * 16 + 2 * cq;
#pragma unroll
        for (int j = 0; j < 8; j++) {
            uint32_t b0 = *(const uint32_t*)&avh[(j * 8 + g) * S2S + k];
            uint32_t b1 = *(const uint32_t*)&avh[(j * 8 + g) * S2S + k + 8];
            MMA16816(o[j], pa[t][0], pa[t][1], pa[t][2], pa[t][3], b0, b1);
        }
    }

    asm volatile("cp.async.wait_group 0;\n");
    __syncthreads();

#pragma unroll
    for (int ri = 0; ri < 2; ri++) {
        int r = ri ? r1 : r0;
        if (r >= Nn) continue;
        float inv = ri ? inv1 : inv0;
        int y = r / Hpix, x = r % Hpix;
        float da[8][2];
#pragma unroll
        for (int j = 0; j < 8; j++) {
            int dl = 8 * j + 2 * cq;
            da[j][0] = bsm[dl];
            da[j][1] = bsm[dl + 1];
        }
#pragma unroll
        for (int tap = 0; tap < 9; tap++) {
            int dy = tap / 3 - 1, dx = tap % 3 - 1;
            int yy = y + dy, xx = x + dx;
            if (yy < 0 || yy >= Hpix || xx < 0 || xx >= Hpix) continue;
            int vrow = r + dy * Hpix + dx - nlo;
#pragma unroll
            for (int j = 0; j < 8; j++) {
                int dl = 8 * j + 2 * cq;
                float2 f = __half22float2(*(const __half2*)&vnb[vrow * S2S + dl]);
                da[j][0] = fmaf(f.x, wsm[tap * 64 + dl], da[j][0]);
                da[j][1] = fmaf(f.y, wsm[tap * 64 + dl + 1], da[j][1]);
            }
        }
#pragma unroll
        for (int j = 0; j < 8; j++) {
            int dl = 8 * j + 2 * cq;
            __half2 v = __floats2half2_rn(o[j][2 * ri] * inv + da[j][0],
                                          o[j][2 * ri + 1] * inv + da[j][1]);
            *(__half2*)&g_acch[((size_t)(b * Nn + r)) * Cc + c0 + dl] = v;
        }
    }
}

// ---------------- launch ----------------
extern "C" void kernel_launch(void* const* d_in, const int* in_sizes, int n_in,
                              void* d_out, int out_size)
{
    const float* x      = (const float*)d_in[0];
    const float* q_w    = (const float*)d_in[1];
    const float* kv_w   = (const float*)d_in[2];
    const float* proj_w = (const float*)d_in[3];
    const float* proj_b = (const float*)d_in[4];
    const float* dwc_w  = (const float*)d_in[5];
    const float* dwc_b  = (const float*)d_in[6];
    const float* an_b   = (const float*)d_in[7];
    const float* na_b   = (const float*)d_in[8];
    const float* ah     = (const float*)d_in[9];
    const float* aw     = (const float*)d_in[10];
    const float* ha     = (const float*)d_in[11];
    const float* wa     = (const float*)d_in[12];

    __half *qkvp, *xhp, *acchp, *wtp;
    cudaGetSymbolAddress((void**)&qkvp, g_qkvh);
    cudaGetSymbolAddress((void**)&xhp, g_xh);
    cudaGetSymbolAddress((void**)&acchp, g_acch);
    cudaGetSymbolAddress((void**)&wtp, g_wTh);

    cudaFuncSetAttribute(gemm_h, cudaFuncAttributeMaxDynamicSharedMemorySize, GT_SMEM);
    cudaFuncSetAttribute(stage1_mma, cudaFuncAttributeMaxDynamicSharedMemorySize, S1_SMEM);
    cudaFuncSetAttribute(stage2_mma, cudaFuncAttributeMaxDynamicSharedMemorySize, S2_SMEM);

    const int M = Bn * Nn;  // 50176

    wtrans_all<<<dim3(2048 / 32, 512 / 32), 256>>>(q_w, kv_w, proj_w, wtp);
    xconv_kernel<<<(int)(((size_t)M * Cc / 8) / 256), 256>>>(x, xhp);
    gemm_h<<<dim3(QKV / 128, M / 128), 256, GT_SMEM>>>(xhp, wtp, nullptr, qkvp,
                                                        M, Cc, QKV, nullptr);
    pool_kernel<<<(Bn * AG * Cc) / 256, 256>>>();
    biasak_kernel<<<(HEADS * AG * Nn) / 256, 256>>>(an_b, ah, aw);
    biasqa_kernel<<<(HEADS * Nn * AG) / 256, 256>>>(na_b, ha, wa);
    stage1_mma<<<Bn * HEADS, 256, S1_SMEM>>>();
    stage2_mma<<<dim3(25, Bn * HEADS), 256, S2_SMEM>>>(dwc_w, dwc_b);
    gemm_h<<<dim3(Cc / 128, M / 128), 256, GT_SMEM>>>(acchp, wtp + WT_PROJ, (float*)d_out,
                                                       nullptr, M, Cc, Cc, proj_b);
}

// round 13
// speedup vs baseline: 1.3746x; 1.0037x over previous
#include <cuda_runtime.h>
#include <cuda_fp16.h>
#include <cstdint>
#include <math.h>

#define Bn 16
#define Nn 3136
#define Cc 512
#define Hpix 56
#define HEADS 8
#define Dd 64
#define AG 49
#define QKV 1536

// ---------------- scratch (device globals; no allocation allowed) ----------------
__device__ __half g_qkvh[(size_t)Bn * Nn * QKV];       // fp16: q[0,512) k[512,1024) v[1024,1536)
__device__ float g_agent[(size_t)Bn * AG * Cc];        // (b,a,c)
__device__ float g_bias_ak[(size_t)HEADS * AG * Nn + 128]; // (h,a,n) +pad for cp.async tail
__device__ float g_bias_qa[(size_t)HEADS * Nn * AG];   // (h,n,a)
__device__ float g_agentv[(size_t)Bn * HEADS * AG * Dd];
__device__ __half g_xh[(size_t)Bn * Nn * Cc];          // x in fp16
__device__ __half g_acch[(size_t)Bn * Nn * Cc];        // attn out + dwc (fp16)
// transposed fp16 weights: [qT|kT|vT] rows 0..1535, projT rows 1536..2047; K-major K=512
__device__ __half g_wTh[(size_t)2048 * 512];
#define WT_PROJ (1536 * 512)

#define MMA16816(acc, a0, a1, a2, a3, b0, b1)                                   \
    asm volatile(                                                               \
        "mma.sync.aligned.m16n8k16.row.col.f32.f16.f16.f32 "                    \
        "{%0,%1,%2,%3}, {%4,%5,%6,%7}, {%8,%9}, {%0,%1,%2,%3};"                 \
        : "+f"(acc[0]), "+f"(acc[1]), "+f"(acc[2]), "+f"(acc[3])                \
        : "r"(a0), "r"(a1), "r"(a2), "r"(a3), "r"(b0), "r"(b1))

#define LDSM_X4(r0, r1, r2, r3, addr)                                           \
    asm volatile("ldmatrix.sync.aligned.m8n8.x4.shared.b16 {%0,%1,%2,%3}, [%4];" \
                 : "=r"(r0), "=r"(r1), "=r"(r2), "=r"(r3) : "r"(addr))

#define CP_ASYNC16(dst, src)                                                    \
    asm volatile("cp.async.cg.shared.global [%0], [%1], 16;\n" :: "r"(dst), "l"(src))

// ---------------- fp16 tensor-core GEMM: C = A[M,K] @ Bt[Nc,K]^T (+bias) ----------
// BM=BN=128 BK=64, 8 warps, 3-stage cp.async, 2 CTAs/SM.  (PINNED config)
#define GAS 72
#define GBUF (128 * GAS)
#define GSTAGES 3
#define GT_SMEM (GSTAGES * 2 * GBUF * 2)   // 110592 bytes

__global__ __launch_bounds__(256, 2) void gemm_h(
    const __half* __restrict__ A, const __half* __restrict__ Bt,
    float* __restrict__ Cout, __half* __restrict__ CoutH,
    int M, int K, int Nc, const float* __restrict__ bias)
{
    extern __shared__ __half smh[];
    __half* smA = smh;
    __half* smB = smh + GSTAGES * GBUF;
    const int tid = threadIdx.x;
    const int wid = tid >> 5, lane = tid & 31;
    const int wm = wid & 3, wn = wid >> 2;
    const int g = lane >> 2, cq = lane & 3;
    const int bm = blockIdx.y * 128, bn = blockIdx.x * 128;

    const uint32_t smA_u = (uint32_t)__cvta_generic_to_shared(smA);
    const uint32_t smB_u = (uint32_t)__cvta_generic_to_shared(smB);
    const uint32_t aOff = (wm * 32 + (lane & 15)) * GAS * 2 + (lane >> 4) * 16;
    const uint32_t bOff = (wn * 64 + (lane & 15)) * GAS * 2 + (lane >> 4) * 16;

    float acc[2][8][4];
#pragma unroll
    for (int i = 0; i < 2; i++)
#pragma unroll
        for (int j = 0; j < 8; j++)
#pragma unroll
            for (int t = 0; t < 4; t++) acc[i][j][t] = 0.f;

    auto loadAB = [&](int s, int kc) {
        const __half* ga = A + (size_t)bm * K + kc * 64;
        const __half* gb = Bt + (size_t)bn * K + kc * 64;
        __half* da = smA + s * GBUF;
        __half* db = smB + s * GBUF;
#pragma unroll
        for (int i = 0; i < 4; i++) {
            int idx = i * 256 + tid;
            int row = idx >> 3, seg = idx & 7;
            uint32_t pa = (uint32_t)__cvta_generic_to_shared(da + row * GAS + seg * 8);
            uint32_t pb = (uint32_t)__cvta_generic_to_shared(db + row * GAS + seg * 8);
            CP_ASYNC16(pa, ga + (size_t)row * K + seg * 8);
            CP_ASYNC16(pb, gb + (size_t)row * K + seg * 8);
        }
        asm volatile("cp.async.commit_group;\n");
    };

    const int KT = K / 64;   // 8
    loadAB(0, 0);
    loadAB(1, 1);
    loadAB(2, 2);

    for (int c = 0; c < KT; c++) {
        int s = c % GSTAGES;
        if (c + 2 < KT)      asm volatile("cp.async.wait_group 2;\n");
        else if (c + 1 < KT) asm volatile("cp.async.wait_group 1;\n");
        else                 asm volatile("cp.async.wait_group 0;\n");
        __syncthreads();
        const uint32_t aP = smA_u + s * (GBUF * 2) + aOff;
        const uint32_t bP = smB_u + s * (GBUF * 2) + bOff;
#pragma unroll
        for (int ks = 0; ks < 4; ks++) {
            const uint32_t kb = ks * 32;
            uint32_t a[2][4];
            LDSM_X4(a[0][0], a[0][1], a[0][2], a[0][3], aP + kb);
            LDSM_X4(a[1][0], a[1][1], a[1][2], a[1][3], aP + 16 * GAS * 2 + kb);
#pragma unroll
            for (int jj = 0; jj < 4; jj++) {
                uint32_t rb0, rb1, rb2, rb3;
                LDSM_X4(rb0, rb1, rb2, rb3, bP + jj * (16 * GAS * 2) + kb);
#pragma unroll
                for (int i = 0; i < 2; i++) {
                    MMA16816(acc[i][2 * jj],     a[i][0], a[i][1], a[i][2], a[i][3], rb0, rb2);
                    MMA16816(acc[i][2 * jj + 1], a[i][0], a[i][1], a[i][2], a[i][3], rb1, rb3);
                }
            }
        }
        __syncthreads();
        if (c + GSTAGES < KT) loadAB(s, c + GSTAGES);
    }

#pragma unroll
    for (int j = 0; j < 8; j++) {
        int col = bn + wn * 64 + j * 8 + 2 * cq;
        float bx = 0.f, by = 0.f;
        if (bias) { bx = bias[col]; by = bias[col + 1]; }
#pragma unroll
        for (int i = 0; i < 2; i++) {
            int r0 = bm + wm * 32 + i * 16 + g;
            if (CoutH) {
                __half2 h0 = __floats2half2_rn(acc[i][j][0] + bx, acc[i][j][1] + by);
                __half2 h1 = __floats2half2_rn(acc[i][j][2] + bx, acc[i][j][3] + by);
                *(__half2*)&CoutH[(size_t)r0 * Nc + col] = h0;
                *(__half2*)&CoutH[(size_t)(r0 + 8) * Nc + col] = h1;
            } else {
                *(float2*)&Cout[(size_t)r0 * Nc + col] =
                    make_float2(acc[i][j][0] + bx, acc[i][j][1] + by);
                *(float2*)&Cout[(size_t)(r0 + 8) * Nc + col] =
                    make_float2(acc[i][j][2] + bx, acc[i][j][3] + by);
            }
        }
    }
}

// ---------------- merged weight transpose (q|kv|proj) -> fp16 K-major -------------
__global__ __launch_bounds__(256) void wtrans_all(
    const float* __restrict__ qw, const float* __restrict__ kvw,
    const float* __restrict__ pw, __half* __restrict__ Wt)
{
    __shared__ float t[32][33];
    int n0 = blockIdx.x * 32, k0 = blockIdx.y * 32;
    const float* W;
    int Nc, col0;
    if (n0 < 512)       { W = qw;  Nc = 512;  col0 = n0; }
    else if (n0 < 1536) { W = kvw; Nc = 1024; col0 = n0 - 512; }
    else                { W = pw;  Nc = 512;  col0 = n0 - 1536; }
    int tx = threadIdx.x & 31, ty = threadIdx.x >> 5;
#pragma unroll
    for (int i = 0; i < 32; i += 8)
        t[ty + i][tx] = W[(size_t)(k0 + ty + i) * Nc + col0 + tx];
    __syncthreads();
#pragma unroll
    for (int i = 0; i < 32; i += 8)
        Wt[(size_t)(n0 + ty + i) * 512 + k0 + tx] = __float2half(t[tx][ty + i]);
}

// ---------------- fp32 -> fp16 cast ----------------
__global__ __launch_bounds__(256) void xconv_kernel(
    const float* __restrict__ src, __half* __restrict__ dst)
{
    size_t i = (size_t)blockIdx.x * 256 + threadIdx.x;
    float4 v0 = ((const float4*)src)[2 * i];
    float4 v1 = ((const float4*)src)[2 * i + 1];
    __half2 h0 = __floats2half2_rn(v0.x, v0.y);
    __half2 h1 = __floats2half2_rn(v0.z, v0.w);
    __half2 h2 = __floats2half2_rn(v1.x, v1.y);
    __half2 h3 = __floats2half2_rn(v1.z, v1.w);
    uint4 o;
    o.x = *(uint32_t*)&h0;
    o.y = *(uint32_t*)&h1;
    o.z = *(uint32_t*)&h2;
    o.w = *(uint32_t*)&h3;
    ((uint4*)dst)[i] = o;
}

// ---------------- 8x8 mean pool, vectorized 8 ch/thread: agent[b,a,c] ------------
// grid = Bn*AG*64 / 256 = 196 blocks exactly.
__global__ __launch_bounds__(256) void pool_kernel()
{
    int idx = blockIdx.x * 256 + threadIdx.x;   // < Bn*AG*64
    int cg = idx & 63;
    int ba = idx >> 6;
    int a = ba % AG;
    int b = ba / AG;
    int c0 = cg * 8;
    int py = a / 7, px = a % 7;

    float acc[8];
#pragma unroll
    for (int i = 0; i < 8; i++) acc[i] = 0.f;

#pragma unroll
    for (int dy = 0; dy < 8; dy++) {
        int n_base = (py * 8 + dy) * Hpix + px * 8;
#pragma unroll
        for (int dx = 0; dx < 8; dx++) {
            uint4 raw = *(const uint4*)&g_qkvh[((size_t)b * Nn + n_base + dx) * QKV + c0];
            float2 f0 = __half22float2(*(__half2*)&raw.x);
            float2 f1 = __half22float2(*(__half2*)&raw.y);
            float2 f2 = __half22float2(*(__half2*)&raw.z);
            float2 f3 = __half22float2(*(__half2*)&raw.w);
            acc[0] += f0.x; acc[1] += f0.y;
            acc[2] += f1.x; acc[3] += f1.y;
            acc[4] += f2.x; acc[5] += f2.y;
            acc[6] += f3.x; acc[7] += f3.y;
        }
    }
    float* out = &g_agent[((size_t)b * AG + a) * Cc + c0];
    *(float4*)out = make_float4(acc[0] * 0.015625f, acc[1] * 0.015625f,
                                acc[2] * 0.015625f, acc[3] * 0.015625f);
    *(float4*)(out + 4) = make_float4(acc[4] * 0.015625f, acc[5] * 0.015625f,
                                      acc[6] * 0.015625f, acc[7] * 0.015625f);
}

// ---------------- bilinear 7x7 -> 56x56 (half-pixel centers, edge clamp) ----------
__device__ __forceinline__ float bilerp7(const float* __restrict__ t, int y, int x)
{
    float sy = (y + 0.5f) * 0.125f - 0.5f;
    float sx = (x + 0.5f) * 0.125f - 0.5f;
    int y0f = (int)floorf(sy);
    int x0f = (int)floorf(sx);
    float wy = sy - (float)y0f;
    float wx = sx - (float)x0f;
    int y0 = min(6, max(0, y0f));
    int y1 = min(6, max(0, y0f + 1));
    int x0 = min(6, max(0, x0f));
    int x1 = min(6, max(0, x0f + 1));
    float v00 = t[y0 * 7 + x0], v01 = t[y0 * 7 + x1];
    float v10 = t[y1 * 7 + x0], v11 = t[y1 * 7 + x1];
    float top = v00 + wx * (v01 - v00);
    float bot = v10 + wx * (v11 - v10);
    return top + wy * (bot - top);
}

// ---------------- merged bias tables (ak then qa) ----------------
#define T_AK (HEADS * AG * Nn)
__global__ __launch_bounds__(256) void bias_all(
    const float* __restrict__ an, const float* __restrict__ ah, const float* __restrict__ aw,
    const float* __restrict__ na, const float* __restrict__ ha, const float* __restrict__ wa)
{
    int idx = blockIdx.x * 256 + threadIdx.x;    // < 2*T_AK (exact)
    if (idx < T_AK) {
        int n = idx % Nn;
        int haa = idx / Nn;
        int y = n / Hpix, x = n % Hpix;
        g_bias_ak[idx] = bilerp7(an + haa * 49, y, x) + ah[haa] + aw[haa];
    } else {
        int i2 = idx - T_AK;
        int a = i2 % AG;
        int hn = i2 / AG;
        int n = hn % Nn;
        int h = hn / Nn;
        int y = n / Hpix, x = n % Hpix;
        int haa = h * AG + a;
        g_bias_qa[i2] = bilerp7(na + haa * 49, y, x) + ha[haa] + wa[haa];
    }
}

// ---------------- stage 1 (flash, tensor cores, double-buffered cp.async) --------
#define FS 72
#define VS 136
#define NCH 25
#define S1_AQ 0
#define S1_KS 9216
#define S1_VS 46080
#define S1_BI 80896
#define S1_SMEM 132640

__global__ __launch_bounds__(256) void stage1_mma()
{
    extern __shared__ char sm1[];
    __half* aq = (__half*)(sm1 + S1_AQ);
    float* mrg = (float*)(sm1 + S1_KS);

    const int bh = blockIdx.x;
    const int b = bh / HEADS, h = bh % HEADS;
    const int tid = threadIdx.x;
    const int wid = tid >> 5, lane = tid & 31;
    const int wm = wid & 3, wn = wid >> 2;
    const int g = lane >> 2, cq = lane & 3;

#pragma unroll
    for (int i = 0; i < 16; i++) {
        int f = i * 256 + tid;
        int a = f >> 6, d = f & 63;
        float v = (a < AG) ? g_agent[((size_t)b * AG + a) * Cc + h * Dd + d] * 0.125f : 0.f;
        aq[a * FS + d] = __float2half(v);
    }

    auto issueKB = [&](int buf, int n0) {
        char* kdst = sm1 + S1_KS + buf * 18432;
#pragma unroll
        for (int i = 0; i < 4; i++) {
            int idx = i * 256 + tid;
            int r = idx >> 3, seg = idx & 7;
            int n = min(n0 + r, Nn - 1);
            uint32_t p = (uint32_t)__cvta_generic_to_shared(kdst + (r * FS + seg * 8) * 2);
            CP_ASYNC16(p, &g_qkvh[((size_t)(b * Nn + n)) * QKV + 512 + h * Dd + seg * 8]);
        }
        char* bdst = sm1 + S1_BI + buf * 25872;
        for (int f = tid; f < AG * 32; f += 256) {
            int a = f >> 5, seg = f & 31;
            uint32_t p = (uint32_t)__cvta_generic_to_shared(bdst + (a * 132 + seg * 4) * 4);
            CP_ASYNC16(p, &g_bias_ak[((size_t)(h * AG + a)) * Nn + n0 + seg * 4]);
        }
        asm volatile("cp.async.commit_group;\n");
    };

    __half2 vxr[8], vyr[8];
    auto loadVregs = [&](int n0) {
#pragma unroll
        for (int i = 0; i < 8; i++) {
            int idx = i * 256 + tid;
            int dp = idx & 31, np = idx >> 5;
            int na = min(n0 + 2 * np, Nn - 1);
            int nb = min(n0 + 2 * np + 1, Nn - 1);
            vxr[i] = *(const __half2*)&g_qkvh[((size_t)(b * Nn + na)) * QKV + 1024 + h * Dd + dp * 2];
            vyr[i] = *(const __half2*)&g_qkvh[((size_t)(b * Nn + nb)) * QKV + 1024 + h * Dd + dp * 2];
        }
    };
    auto stsV = [&](int buf) {
        __half* vd = (__half*)(sm1 + S1_VS + buf * 17408);
#pragma unroll
        for (int i = 0; i < 8; i++) {
            int idx = i * 256 + tid;
            int dp = idx & 31, np = idx >> 5;
            *(__half2*)&vd[(2 * dp) * VS + 2 * np] = __lows2half2(vxr[i], vyr[i]);
            *(__half2*)&vd[(2 * dp + 1) * VS + 2 * np] = __highs2half2(vxr[i], vyr[i]);
        }
    };

    float m0 = -1e30f, m1 = -1e30f, l0 = 0.f, l1 = 0.f;
    float o[8][4];
#pragma unroll
    for (int j = 0; j < 8; j++)
#pragma unroll
        for (int t = 0; t < 4; t++) o[j][t] = 0.f;

    const int a0r = wm * 16 + g, a1r = a0r + 8;

    issueKB(0, 0);
    loadVregs(0);
    asm volatile("cp.async.wait_group 0;\n");
    stsV(0);
    __syncthreads();

    for (int c = 0; c < NCH; c++) {
        const int cur = c & 1, nxt = cur ^ 1;
        const int n0 = c * 128;
        if (c + 1 < NCH) {
            issueKB(nxt, (c + 1) * 128);
            loadVregs((c + 1) * 128);
        }
        const __half* ksb = (const __half*)(sm1 + S1_KS + cur * 18432);
        const __half* vsb = (const __half*)(sm1 + S1_VS + cur * 17408);
        const float* bib = (const float*)(sm1 + S1_BI + cur * 25872);

        float s[8][4];
#pragma unroll
        for (int j = 0; j < 8; j++)
#pragma unroll
            for (int t = 0; t < 4; t++) s[j][t] = 0.f;
#pragma unroll
        for (int t = 0; t < 4; t++) {
            int kk = t * 16 + 2 * cq;
            uint32_t A0 = *(const uint32_t*)&aq[(wm * 16 + g) * FS + kk];
            uint32_t A1 = *(const uint32_t*)&aq[(wm * 16 + g + 8) * FS + kk];
            uint32_t A2 = *(const uint32_t*)&aq[(wm * 16 + g) * FS + kk + 8];
            uint32_t A3 = *(const uint32_t*)&aq[(wm * 16 + g + 8) * FS + kk + 8];
#pragma unroll
            for (int j = 0; j < 8; j++) {
                int row = wn * 64 + j * 8 + g;
                uint32_t b0 = *(const uint32_t*)&ksb[row * FS + kk];
                uint32_t b1 = *(const uint32_t*)&ksb[row * FS + kk + 8];
                MMA16816(s[j], A0, A1, A2, A3, b0, b1);
            }
        }

        float cm0 = -1e30f, cm1 = -1e30f;
#pragma unroll
        for (int j = 0; j < 8; j++) {
            int nl = wn * 64 + j * 8 + 2 * cq;
            int n = n0 + nl;
            bool v0 = (n < Nn), v1 = (n + 1 < Nn);
            float ba00 = (a0r < AG) ? bib[a0r * 132 + nl] : 0.f;
            float ba01 = (a0r < AG) ? bib[a0r * 132 + nl + 1] : 0.f;
            float ba10 = (a1r < AG) ? bib[a1r * 132 + nl] : 0.f;
            float ba11 = (a1r < AG) ? bib[a1r * 132 + nl + 1] : 0.f;
            s[j][0] = v0 ? s[j][0] + ba00 : -1e30f;
            s[j][1] = v1 ? s[j][1] + ba01 : -1e30f;
            s[j][2] = v0 ? s[j][2] + ba10 : -1e30f;
            s[j][3] = v1 ? s[j][3] + ba11 : -1e30f;
            cm0 = fmaxf(cm0, fmaxf(s[j][0], s[j][1]));
            cm1 = fmaxf(cm1, fmaxf(s[j][2], s[j][3]));
        }
        cm0 = fmaxf(cm0, __shfl_xor_sync(0xffffffffu, cm0, 1));
        cm0 = fmaxf(cm0, __shfl_xor_sync(0xffffffffu, cm0, 2));
        cm1 = fmaxf(cm1, __shfl_xor_sync(0xffffffffu, cm1, 1));
        cm1 = fmaxf(cm1, __shfl_xor_sync(0xffffffffu, cm1, 2));

        float M0 = fmaxf(m0, cm0), M1 = fmaxf(m1, cm1);
        float r0 = __expf(m0 - M0), r1 = __expf(m1 - M1);
        float sum0 = 0.f, sum1 = 0.f;
#pragma unroll
        for (int j = 0; j < 8; j++) {
            s[j][0] = __expf(s[j][0] - M0);
            s[j][1] = __expf(s[j][1] - M0);
            s[j][2] = __expf(s[j][2] - M1);
            s[j][3] = __expf(s[j][3] - M1);
            sum0 += s[j][0] + s[j][1];
            sum1 += s[j][2] + s[j][3];
        }
        sum0 += __shfl_xor_sync(0xffffffffu, sum0, 1);
        sum0 += __shfl_xor_sync(0xffffffffu, sum0, 2);
        sum1 += __shfl_xor_sync(0xffffffffu, sum1, 1);
        sum1 += __shfl_xor_sync(0xffffffffu, sum1, 2);
        l0 = l0 * r0 + sum0;
        l1 = l1 * r1 + sum1;
        m0 = M0;
        m1 = M1;
#pragma unroll
        for (int j = 0; j < 8; j++) {
            o[j][0] *= r0; o[j][1] *= r0;
            o[j][2] *= r1; o[j][3] *= r1;
        }

        uint32_t pa[4][4];
#pragma unroll
        for (int t = 0; t < 4; t++) {
            __half2 h0 = __floats2half2_rn(s[2 * t][0], s[2 * t][1]);
            __half2 h1 = __floats2half2_rn(s[2 * t][2], s[2 * t][3]);
            __half2 h2 = __floats2half2_rn(s[2 * t + 1][0], s[2 * t + 1][1]);
            __half2 h3 = __floats2half2_rn(s[2 * t + 1][2], s[2 * t + 1][3]);
            pa[t][0] = *(uint32_t*)&h0;
            pa[t][1] = *(uint32_t*)&h1;
            pa[t][2] = *(uint32_t*)&h2;
            pa[t][3] = *(uint32_t*)&h3;
        }

#pragma unroll
        for (int t = 0; t < 4; t++) {
            int kk = wn * 64 + t * 16 + 2 * cq;
#pragma unroll
            for (int j = 0; j < 8; j++) {
                uint32_t b0 = *(const uint32_t*)&vsb[(j * 8 + g) * VS + kk];
                uint32_t b1 = *(const uint32_t*)&vsb[(j * 8 + g) * VS + kk + 8];
                MMA16816(o[j], pa[t][0], pa[t][1], pa[t][2], pa[t][3], b0, b1);
            }
        }

        if (c + 1 < NCH) {
            asm volatile("cp.async.wait_group 0;\n");
            stsV(nxt);
            __syncthreads();
        }
    }

    __syncthreads();
    float* p = mrg + ((size_t)(wm * 32 + lane)) * 36;
    if (wn == 1) {
#pragma unroll
        for (int j = 0; j < 8; j++) {
            p[4 * j] = o[j][0]; p[4 * j + 1] = o[j][1];
            p[4 * j + 2] = o[j][2]; p[4 * j + 3] = o[j][3];
        }
        p[32] = m0; p[33] = m1; p[34] = l0; p[35] = l1;
    }
    __syncthreads();
    if (wn == 0) {
        float pm0 = p[32], pm1 = p[33], pl0 = p[34], pl1 = p[35];
        float M0 = fmaxf(m0, pm0), M1 = fmaxf(m1, pm1);
        float ra0 = __expf(m0 - M0), rb0 = __expf(pm0 - M0);
        float ra1 = __expf(m1 - M1), rb1 = __expf(pm1 - M1);
        float i0 = 1.0f / (l0 * ra0 + pl0 * rb0);
        float i1 = 1.0f / (l1 * ra1 + pl1 * rb1);
#pragma unroll
        for (int j = 0; j < 8; j++) {
            int d = j * 8 + 2 * cq;
            if (a0r < AG) {
                float2 v = make_float2((o[j][0] * ra0 + p[4 * j] * rb0) * i0,
                                       (o[j][1] * ra0 + p[4 * j + 1] * rb0) * i0);
                *(float2*)&g_agentv[((size_t)bh * AG + a0r) * Dd + d] = v;
            }
            if (a1r < AG) {
                float2 v = make_float2((o[j][2] * ra1 + p[4 * j + 2] * rb1) * i1,
                                       (o[j][3] * ra1 + p[4 * j + 3] * rb1) * i1);
                *(float2*)&g_agentv[((size_t)bh * AG + a1r) * Dd + d] = v;
            }
        }
    }
}

// ---------------- stage 2 + fused dwc: out = softmax(q·a^T+b)@agent_v + conv(v) ---
#define S2S 72
#define S2_QH 0
#define S2_A4 18432
#define S2_AV 27648
#define S2_VN 36864
#define S2_WS 71712
#define S2_BS 74016
#define S2_SMEM 74272

__global__ __launch_bounds__(256) void stage2_mma(
    const float* __restrict__ dwc_w, const float* __restrict__ dwc_b)
{
    extern __shared__ char sm2[];
    __half* qh  = (__half*)(sm2 + S2_QH);
    __half* a4h = (__half*)(sm2 + S2_A4);
    __half* avh = (__half*)(sm2 + S2_AV);
    __half* vnb = (__half*)(sm2 + S2_VN);
    float* wsm  = (float*)(sm2 + S2_WS);
    float* bsm  = (float*)(sm2 + S2_BS);

    const int bh = blockIdx.y;
    const int b = bh / HEADS, h = bh % HEADS;
    const int n0 = blockIdx.x * 128;
    const int tid = threadIdx.x;
    const int wid = tid >> 5, lane = tid & 31;
    const int g = lane >> 2, cq = lane & 3;
    const int c0 = h * Dd;
    const int nlo = n0 - 57;

#pragma unroll
    for (int i = 0; i < 8; i++) {
        int idx = i * 256 + tid;
        if (idx < 242 * 8) {
            int r = idx >> 3, seg = idx & 7;
            int n = min(max(nlo + r, 0), Nn - 1);
            uint32_t p = (uint32_t)__cvta_generic_to_shared(vnb + r * S2S + seg * 8);
            CP_ASYNC16(p, &g_qkvh[((size_t)(b * Nn + n)) * QKV + 1024 + c0 + seg * 8]);
        }
    }
    asm volatile("cp.async.commit_group;\n");

#pragma unroll
    for (int i = 0; i < 4; i++) {
        int idx = i * 256 + tid;
        int r = idx >> 3, seg = idx & 7;
        int n = min(n0 + r, Nn - 1);
        *(uint4*)&qh[r * S2S + seg * 8] =
            *(const uint4*)&g_qkvh[((size_t)(b * Nn + n)) * QKV + c0 + seg * 8];
    }
#pragma unroll
    for (int i = 0; i < 16; i++) {
        int idx = i * 256 + tid;
        int a = idx >> 6, d = idx & 63;
        float av = (a < AG) ? g_agent[((size_t)b * AG + a) * Cc + c0 + d] * 0.125f : 0.f;
        float vv = (a < AG) ? g_agentv[((size_t)bh * AG + a) * Dd + d] : 0.f;
        a4h[a * S2S + d] = __float2half(av);
        avh[d * S2S + a] = __float2half(vv);
    }
    for (int i = tid; i < 9 * 64; i += 256) {
        int c = i & 63, tap = i >> 6;
        wsm[tap * 64 + c] = dwc_w[(c0 + c) * 9 + tap];
    }
    if (tid < 64) bsm[tid] = dwc_b[c0 + tid];
    __syncthreads();

    float s[8][4];
#pragma unroll
    for (int j = 0; j < 8; j++)
#pragma unroll
        for (int t = 0; t < 4; t++) s[j][t] = 0.f;

    const __half* qa = qh + (wid * 16) * S2S;
#pragma unroll
    for (int t = 0; t < 4; t++) {
        int k = t * 16 + 2 * cq;
        uint32_t a0 = *(const uint32_t*)&qa[g * S2S + k];
        uint32_t a1 = *(const uint32_t*)&qa[(g + 8) * S2S + k];
        uint32_t a2 = *(const uint32_t*)&qa[g * S2S + k + 8];
        uint32_t a3 = *(const uint32_t*)&qa[(g + 8) * S2S + k + 8];
#pragma unroll
        for (int j = 0; j < 8; j++) {
            uint32_t b0 = *(const uint32_t*)&a4h[(j * 8 + g) * S2S + k];
            uint32_t b1 = *(const uint32_t*)&a4h[(j * 8 + g) * S2S + k + 8];
            MMA16816(s[j], a0, a1, a2, a3, b0, b1);
        }
    }

    const int r0 = n0 + wid * 16 + g;
    const int r1 = r0 + 8;
    float m0 = -1e30f, m1 = -1e30f;
#pragma unroll
    for (int j = 0; j < 8; j++) {
        int a = 8 * j + 2 * cq;
        if (a < AG) {
            float b00 = (r0 < Nn) ? g_bias_qa[((size_t)h * Nn + r0) * AG + a] : 0.f;
            float b10 = (r1 < Nn) ? g_bias_qa[((size_t)h * Nn + r1) * AG + a] : 0.f;
            s[j][0] += b00;
            s[j][2] += b10;
            if (a + 1 < AG) {
                float b01 = (r0 < Nn) ? g_bias_qa[((size_t)h * Nn + r0) * AG + a + 1] : 0.f;
                float b11 = (r1 < Nn) ? g_bias_qa[((size_t)h * Nn + r1) * AG + a + 1] : 0.f;
                s[j][1] += b01;
                s[j][3] += b11;
            } else {
                s[j][1] = -1e30f;
                s[j][3] = -1e30f;
            }
        } else {
            s[j][0] = -1e30f; s[j][1] = -1e30f;
            s[j][2] = -1e30f; s[j][3] = -1e30f;
        }
        m0 = fmaxf(m0, fmaxf(s[j][0], s[j][1]));
        m1 = fmaxf(m1, fmaxf(s[j][2], s[j][3]));
    }
    m0 = fmaxf(m0, __shfl_xor_sync(0xffffffffu, m0, 1));
    m0 = fmaxf(m0, __shfl_xor_sync(0xffffffffu, m0, 2));
    m1 = fmaxf(m1, __shfl_xor_sync(0xffffffffu, m1, 1));
    m1 = fmaxf(m1, __shfl_xor_sync(0xffffffffu, m1, 2));

    float sum0 = 0.f, sum1 = 0.f;
#pragma unroll
    for (int j = 0; j < 8; j++) {
        s[j][0] = __expf(s[j][0] - m0);
        s[j][1] = __expf(s[j][1] - m0);
        s[j][2] = __expf(s[j][2] - m1);
        s[j][3] = __expf(s[j][3] - m1);
        sum0 += s[j][0] + s[j][1];
        sum1 += s[j][2] + s[j][3];
    }
    sum0 += __shfl_xor_sync(0xffffffffu, sum0, 1);
    sum0 += __shfl_xor_sync(0xffffffffu, sum0, 2);
    sum1 += __shfl_xor_sync(0xffffffffu, sum1, 1);
    sum1 += __shfl_xor_sync(0xffffffffu, sum1, 2);
    const float inv0 = 1.0f / sum0, inv1 = 1.0f / sum1;

    uint32_t pa[4][4];
#pragma unroll
    for (int t = 0; t < 4; t++) {
        __half2 h0 = __floats2half2_rn(s[2 * t][0], s[2 * t][1]);
        __half2 h1 = __floats2half2_rn(s[2 * t][2], s[2 * t][3]);
        __half2 h2 = __floats2half2_rn(s[2 * t + 1][0], s[2 * t + 1][1]);
        __half2 h3 = __floats2half2_rn(s[2 * t + 1][2], s[2 * t + 1][3]);
        pa[t][0] = *(uint32_t*)&h0;
        pa[t][1] = *(uint32_t*)&h1;
        pa[t][2] = *(uint32_t*)&h2;
        pa[t][3] = *(uint32_t*)&h3;
    }

    float o[8][4];
#pragma unroll
    for (int j = 0; j < 8; j++)
#pragma unroll
        for (int t = 0; t < 4; t++) o[j][t] = 0.f;
#pragma unroll
    for (int t = 0; t < 4; t++) {
        int k = t * 16 + 2 * cq;
#pragma unroll
        for (int j = 0; j < 8; j++) {
            uint32_t b0 = *(const uint32_t*)&avh[(j * 8 + g) * S2S + k];
            uint32_t b1 = *(const uint32_t*)&avh[(j * 8 + g) * S2S + k + 8];
            MMA16816(o[j], pa[t][0], pa[t][1], pa[t][2], pa[t][3], b0, b1);
        }
    }

    asm volatile("cp.async.wait_group 0;\n");
    __syncthreads();

#pragma unroll
    for (int ri = 0; ri < 2; ri++) {
        int r = ri ? r1 : r0;
        if (r >= Nn) continue;
        float inv = ri ? inv1 : inv0;
        int y = r / Hpix, x = r % Hpix;
        float da[8][2];
#pragma unroll
        for (int j = 0; j < 8; j++) {
            int dl = 8 * j + 2 * cq;
            da[j][0] = bsm[dl];
            da[j][1] = bsm[dl + 1];
        }
#pragma unroll
        for (int tap = 0; tap < 9; tap++) {
            int dy = tap / 3 - 1, dx = tap % 3 - 1;
            int yy = y + dy, xx = x + dx;
            if (yy < 0 || yy >= Hpix || xx < 0 || xx >= Hpix) continue;
            int vrow = r + dy * Hpix + dx - nlo;
#pragma unroll
            for (int j = 0; j < 8; j++) {
                int dl = 8 * j + 2 * cq;
                float2 f = __half22float2(*(const __half2*)&vnb[vrow * S2S + dl]);
                da[j][0] = fmaf(f.x, wsm[tap * 64 + dl], da[j][0]);
                da[j][1] = fmaf(f.y, wsm[tap * 64 + dl + 1], da[j][1]);
            }
        }
#pragma unroll
        for (int j = 0; j < 8; j++) {
            int dl = 8 * j + 2 * cq;
            __half2 v = __floats2half2_rn(o[j][2 * ri] * inv + da[j][0],
                                          o[j][2 * ri + 1] * inv + da[j][1]);
            *(__half2*)&g_acch[((size_t)(b * Nn + r)) * Cc + c0 + dl] = v;
        }
    }
}

// ---------------- launch ----------------
extern "C" void kernel_launch(void* const* d_in, const int* in_sizes, int n_in,
                              void* d_out, int out_size)
{
    const float* x      = (const float*)d_in[0];
    const float* q_w    = (const float*)d_in[1];
    const float* kv_w   = (const float*)d_in[2];
    const float* proj_w = (const float*)d_in[3];
    const float* proj_b = (const float*)d_in[4];
    const float* dwc_w  = (const float*)d_in[5];
    const float* dwc_b  = (const float*)d_in[6];
    const float* an_b   = (const float*)d_in[7];
    const float* na_b   = (const float*)d_in[8];
    const float* ah     = (const float*)d_in[9];
    const float* aw     = (const float*)d_in[10];
    const float* ha     = (const float*)d_in[11];
    const float* wa     = (const float*)d_in[12];

    __half *qkvp, *xhp, *acchp, *wtp;
    cudaGetSymbolAddress((void**)&qkvp, g_qkvh);
    cudaGetSymbolAddress((void**)&xhp, g_xh);
    cudaGetSymbolAddress((void**)&acchp, g_acch);
    cudaGetSymbolAddress((void**)&wtp, g_wTh);

    cudaFuncSetAttribute(gemm_h, cudaFuncAttributeMaxDynamicSharedMemorySize, GT_SMEM);
    cudaFuncSetAttribute(stage1_mma, cudaFuncAttributeMaxDynamicSharedMemorySize, S1_SMEM);
    cudaFuncSetAttribute(stage2_mma, cudaFuncAttributeMaxDynamicSharedMemorySize, S2_SMEM);

    const int M = Bn * Nn;  // 50176

    wtrans_all<<<dim3(2048 / 32, 512 / 32), 256>>>(q_w, kv_w, proj_w, wtp);
    xconv_kernel<<<(int)(((size_t)M * Cc / 8) / 256), 256>>>(x, xhp);
    gemm_h<<<dim3(QKV / 128, M / 128), 256, GT_SMEM>>>(xhp, wtp, nullptr, qkvp,
                                                        M, Cc, QKV, nullptr);
    pool_kernel<<<(Bn * AG * 64) / 256, 256>>>();
    bias_all<<<(2 * T_AK) / 256, 256>>>(an_b, ah, aw, na_b, ha, wa);
    stage1_mma<<<Bn * HEADS, 256, S1_SMEM>>>();
    stage2_mma<<<dim3(25, Bn * HEADS), 256, S2_SMEM>>>(dwc_w, dwc_b);
    gemm_h<<<dim3(Cc / 128, M / 128), 256, GT_SMEM>>>(acchp, wtp + WT_PROJ, (float*)d_out,
                                                       nullptr, M, Cc, Cc, proj_b);
}

// round 14
// speedup vs baseline: 1.3928x; 1.0132x over previous
#include <cuda_runtime.h>
#include <cuda_fp16.h>
#include <cstdint>
#include <math.h>

#define Bn 16
#define Nn 3136
#define Cc 512
#define Hpix 56
#define HEADS 8
#define Dd 64
#define AG 49
#define QKV 1536

// ---------------- scratch (device globals; no allocation allowed) ----------------
__device__ __half g_qkvh[(size_t)Bn * Nn * QKV];       // fp16: q[0,512) k[512,1024) v[1024,1536)
__device__ float g_agent[(size_t)Bn * AG * Cc];        // (b,a,c) written by stage1
__device__ float g_bias_ak[(size_t)HEADS * AG * Nn + 128]; // (h,a,n) +pad for cp.async tail
__device__ float g_bias_qa[(size_t)HEADS * Nn * AG];   // (h,n,a)
__device__ float g_agentv[(size_t)Bn * HEADS * AG * Dd];
__device__ __half g_xh[(size_t)Bn * Nn * Cc];          // x in fp16
__device__ __half g_acch[(size_t)Bn * Nn * Cc];        // attn out + dwc (fp16)
// transposed fp16 weights: [qT|kT|vT] rows 0..1535, projT rows 1536..2047; K-major K=512
__device__ __half g_wTh[(size_t)2048 * 512];
#define WT_PROJ (1536 * 512)

#define MMA16816(acc, a0, a1, a2, a3, b0, b1)                                   \
    asm volatile(                                                               \
        "mma.sync.aligned.m16n8k16.row.col.f32.f16.f16.f32 "                    \
        "{%0,%1,%2,%3}, {%4,%5,%6,%7}, {%8,%9}, {%0,%1,%2,%3};"                 \
        : "+f"(acc[0]), "+f"(acc[1]), "+f"(acc[2]), "+f"(acc[3])                \
        : "r"(a0), "r"(a1), "r"(a2), "r"(a3), "r"(b0), "r"(b1))

#define LDSM_X4(r0, r1, r2, r3, addr)                                           \
    asm volatile("ldmatrix.sync.aligned.m8n8.x4.shared.b16 {%0,%1,%2,%3}, [%4];" \
                 : "=r"(r0), "=r"(r1), "=r"(r2), "=r"(r3) : "r"(addr))

#define CP_ASYNC16(dst, src)                                                    \
    asm volatile("cp.async.cg.shared.global [%0], [%1], 16;\n" :: "r"(dst), "l"(src))

// ---------------- fp16 tensor-core GEMM: C = A[M,K] @ Bt[Nc,K]^T (+bias) ----------
// BM=BN=128 BK=64, 8 warps, 3-stage cp.async, 2 CTAs/SM.  (PINNED config)
#define GAS 72
#define GBUF (128 * GAS)
#define GSTAGES 3
#define GT_SMEM (GSTAGES * 2 * GBUF * 2)   // 110592 bytes

__global__ __launch_bounds__(256, 2) void gemm_h(
    const __half* __restrict__ A, const __half* __restrict__ Bt,
    float* __restrict__ Cout, __half* __restrict__ CoutH,
    int M, int K, int Nc, const float* __restrict__ bias)
{
    extern __shared__ __half smh[];
    __half* smA = smh;
    __half* smB = smh + GSTAGES * GBUF;
    const int tid = threadIdx.x;
    const int wid = tid >> 5, lane = tid & 31;
    const int wm = wid & 3, wn = wid >> 2;
    const int g = lane >> 2, cq = lane & 3;
    const int bm = blockIdx.y * 128, bn = blockIdx.x * 128;

    const uint32_t smA_u = (uint32_t)__cvta_generic_to_shared(smA);
    const uint32_t smB_u = (uint32_t)__cvta_generic_to_shared(smB);
    const uint32_t aOff = (wm * 32 + (lane & 15)) * GAS * 2 + (lane >> 4) * 16;
    const uint32_t bOff = (wn * 64 + (lane & 15)) * GAS * 2 + (lane >> 4) * 16;

    float acc[2][8][4];
#pragma unroll
    for (int i = 0; i < 2; i++)
#pragma unroll
        for (int j = 0; j < 8; j++)
#pragma unroll
            for (int t = 0; t < 4; t++) acc[i][j][t] = 0.f;

    auto loadAB = [&](int s, int kc) {
        const __half* ga = A + (size_t)bm * K + kc * 64;
        const __half* gb = Bt + (size_t)bn * K + kc * 64;
        __half* da = smA + s * GBUF;
        __half* db = smB + s * GBUF;
#pragma unroll
        for (int i = 0; i < 4; i++) {
            int idx = i * 256 + tid;
            int row = idx >> 3, seg = idx & 7;
            uint32_t pa = (uint32_t)__cvta_generic_to_shared(da + row * GAS + seg * 8);
            uint32_t pb = (uint32_t)__cvta_generic_to_shared(db + row * GAS + seg * 8);
            CP_ASYNC16(pa, ga + (size_t)row * K + seg * 8);
            CP_ASYNC16(pb, gb + (size_t)row * K + seg * 8);
        }
        asm volatile("cp.async.commit_group;\n");
    };

    const int KT = K / 64;   // 8
    loadAB(0, 0);
    loadAB(1, 1);
    loadAB(2, 2);

    for (int c = 0; c < KT; c++) {
        int s = c % GSTAGES;
        if (c + 2 < KT)      asm volatile("cp.async.wait_group 2;\n");
        else if (c + 1 < KT) asm volatile("cp.async.wait_group 1;\n");
        else                 asm volatile("cp.async.wait_group 0;\n");
        __syncthreads();
        const uint32_t aP = smA_u + s * (GBUF * 2) + aOff;
        const uint32_t bP = smB_u + s * (GBUF * 2) + bOff;
#pragma unroll
        for (int ks = 0; ks < 4; ks++) {
            const uint32_t kb = ks * 32;
            uint32_t a[2][4];
            LDSM_X4(a[0][0], a[0][1], a[0][2], a[0][3], aP + kb);
            LDSM_X4(a[1][0], a[1][1], a[1][2], a[1][3], aP + 16 * GAS * 2 + kb);
#pragma unroll
            for (int jj = 0; jj < 4; jj++) {
                uint32_t rb0, rb1, rb2, rb3;
                LDSM_X4(rb0, rb1, rb2, rb3, bP + jj * (16 * GAS * 2) + kb);
#pragma unroll
                for (int i = 0; i < 2; i++) {
                    MMA16816(acc[i][2 * jj],     a[i][0], a[i][1], a[i][2], a[i][3], rb0, rb2);
                    MMA16816(acc[i][2 * jj + 1], a[i][0], a[i][1], a[i][2], a[i][3], rb1, rb3);
                }
            }
        }
        __syncthreads();
        if (c + GSTAGES < KT) loadAB(s, c + GSTAGES);
    }

#pragma unroll
    for (int j = 0; j < 8; j++) {
        int col = bn + wn * 64 + j * 8 + 2 * cq;
        float bx = 0.f, by = 0.f;
        if (bias) { bx = bias[col]; by = bias[col + 1]; }
#pragma unroll
        for (int i = 0; i < 2; i++) {
            int r0 = bm + wm * 32 + i * 16 + g;
            if (CoutH) {
                __half2 h0 = __floats2half2_rn(acc[i][j][0] + bx, acc[i][j][1] + by);
                __half2 h1 = __floats2half2_rn(acc[i][j][2] + bx, acc[i][j][3] + by);
                *(__half2*)&CoutH[(size_t)r0 * Nc + col] = h0;
                *(__half2*)&CoutH[(size_t)(r0 + 8) * Nc + col] = h1;
            } else {
                *(float2*)&Cout[(size_t)r0 * Nc + col] =
                    make_float2(acc[i][j][0] + bx, acc[i][j][1] + by);
                *(float2*)&Cout[(size_t)(r0 + 8) * Nc + col] =
                    make_float2(acc[i][j][2] + bx, acc[i][j][3] + by);
            }
        }
    }
}

// ---------------- merged weight transpose (q|kv|proj) -> fp16 K-major -------------
__global__ __launch_bounds__(256) void wtrans_all(
    const float* __restrict__ qw, const float* __restrict__ kvw,
    const float* __restrict__ pw, __half* __restrict__ Wt)
{
    __shared__ float t[32][33];
    int n0 = blockIdx.x * 32, k0 = blockIdx.y * 32;
    const float* W;
    int Nc, col0;
    if (n0 < 512)       { W = qw;  Nc = 512;  col0 = n0; }
    else if (n0 < 1536) { W = kvw; Nc = 1024; col0 = n0 - 512; }
    else                { W = pw;  Nc = 512;  col0 = n0 - 1536; }
    int tx = threadIdx.x & 31, ty = threadIdx.x >> 5;
#pragma unroll
    for (int i = 0; i < 32; i += 8)
        t[ty + i][tx] = W[(size_t)(k0 + ty + i) * Nc + col0 + tx];
    __syncthreads();
#pragma unroll
    for (int i = 0; i < 32; i += 8)
        Wt[(size_t)(n0 + ty + i) * 512 + k0 + tx] = __float2half(t[tx][ty + i]);
}

// ---------------- fp32 -> fp16 cast ----------------
__global__ __launch_bounds__(256) void xconv_kernel(
    const float* __restrict__ src, __half* __restrict__ dst)
{
    size_t i = (size_t)blockIdx.x * 256 + threadIdx.x;
    float4 v0 = ((const float4*)src)[2 * i];
    float4 v1 = ((const float4*)src)[2 * i + 1];
    __half2 h0 = __floats2half2_rn(v0.x, v0.y);
    __half2 h1 = __floats2half2_rn(v0.z, v0.w);
    __half2 h2 = __floats2half2_rn(v1.x, v1.y);
    __half2 h3 = __floats2half2_rn(v1.z, v1.w);
    uint4 o;
    o.x = *(uint32_t*)&h0;
    o.y = *(uint32_t*)&h1;
    o.z = *(uint32_t*)&h2;
    o.w = *(uint32_t*)&h3;
    ((uint4*)dst)[i] = o;
}

// ---------------- bilinear 7x7 -> 56x56 (half-pixel centers, edge clamp) ----------
__device__ __forceinline__ float bilerp7(const float* __restrict__ t, int y, int x)
{
    float sy = (y + 0.5f) * 0.125f - 0.5f;
    float sx = (x + 0.5f) * 0.125f - 0.5f;
    int y0f = (int)floorf(sy);
    int x0f = (int)floorf(sx);
    float wy = sy - (float)y0f;
    float wx = sx - (float)x0f;
    int y0 = min(6, max(0, y0f));
    int y1 = min(6, max(0, y0f + 1));
    int x0 = min(6, max(0, x0f));
    int x1 = min(6, max(0, x0f + 1));
    float v00 = t[y0 * 7 + x0], v01 = t[y0 * 7 + x1];
    float v10 = t[y1 * 7 + x0], v11 = t[y1 * 7 + x1];
    float top = v00 + wx * (v01 - v00);
    float bot = v10 + wx * (v11 - v10);
    return top + wy * (bot - top);
}

// ---------------- merged bias tables (ak then qa) ----------------
#define T_AK (HEADS * AG * Nn)
__global__ __launch_bounds__(256) void bias_all(
    const float* __restrict__ an, const float* __restrict__ ah, const float* __restrict__ aw,
    const float* __restrict__ na, const float* __restrict__ ha, const float* __restrict__ wa)
{
    int idx = blockIdx.x * 256 + threadIdx.x;    // < 2*T_AK (exact)
    if (idx < T_AK) {
        int n = idx % Nn;
        int haa = idx / Nn;
        int y = n / Hpix, x = n % Hpix;
        g_bias_ak[idx] = bilerp7(an + haa * 49, y, x) + ah[haa] + aw[haa];
    } else {
        int i2 = idx - T_AK;
        int a = i2 % AG;
        int hn = i2 / AG;
        int n = hn % Nn;
        int h = hn / Nn;
        int y = n / Hpix, x = n % Hpix;
        int haa = h * AG + a;
        g_bias_qa[i2] = bilerp7(na + haa * 49, y, x) + ha[haa] + wa[haa];
    }
}

// ---------------- stage 1 (flash, tensor cores) + fused agent pooling -------------
// Each block (b,h) pools its own agent slice from q (disjoint across blocks),
// stores fp32 g_agent for stage2, and runs flash attention over K/V chunks.
#define FS 72
#define VS 136
#define NCH 25
#define S1_AQ 0
#define S1_KS 9216
#define S1_VS 46080
#define S1_BI 80896
#define S1_SMEM 132640

__global__ __launch_bounds__(256) void stage1_mma()
{
    extern __shared__ char sm1[];
    __half* aq = (__half*)(sm1 + S1_AQ);
    float* mrg = (float*)(sm1 + S1_KS);

    const int bh = blockIdx.x;
    const int b = bh / HEADS, h = bh % HEADS;
    const int tid = threadIdx.x;
    const int wid = tid >> 5, lane = tid & 31;
    const int wm = wid & 3, wn = wid >> 2;
    const int g = lane >> 2, cq = lane & 3;

    auto issueKB = [&](int buf, int n0) {
        char* kdst = sm1 + S1_KS + buf * 18432;
#pragma unroll
        for (int i = 0; i < 4; i++) {
            int idx = i * 256 + tid;
            int r = idx >> 3, seg = idx & 7;
            int n = min(n0 + r, Nn - 1);
            uint32_t p = (uint32_t)__cvta_generic_to_shared(kdst + (r * FS + seg * 8) * 2);
            CP_ASYNC16(p, &g_qkvh[((size_t)(b * Nn + n)) * QKV + 512 + h * Dd + seg * 8]);
        }
        char* bdst = sm1 + S1_BI + buf * 25872;
        for (int f = tid; f < AG * 32; f += 256) {
            int a = f >> 5, seg = f & 31;
            uint32_t p = (uint32_t)__cvta_generic_to_shared(bdst + (a * 132 + seg * 4) * 4);
            CP_ASYNC16(p, &g_bias_ak[((size_t)(h * AG + a)) * Nn + n0 + seg * 4]);
        }
        asm volatile("cp.async.commit_group;\n");
    };

    __half2 vxr[8], vyr[8];
    auto loadVregs = [&](int n0) {
#pragma unroll
        for (int i = 0; i < 8; i++) {
            int idx = i * 256 + tid;
            int dp = idx & 31, np = idx >> 5;
            int na = min(n0 + 2 * np, Nn - 1);
            int nb = min(n0 + 2 * np + 1, Nn - 1);
            vxr[i] = *(const __half2*)&g_qkvh[((size_t)(b * Nn + na)) * QKV + 1024 + h * Dd + dp * 2];
            vyr[i] = *(const __half2*)&g_qkvh[((size_t)(b * Nn + nb)) * QKV + 1024 + h * Dd + dp * 2];
        }
    };
    auto stsV = [&](int buf) {
        __half* vd = (__half*)(sm1 + S1_VS + buf * 17408);
#pragma unroll
        for (int i = 0; i < 8; i++) {
            int idx = i * 256 + tid;
            int dp = idx & 31, np = idx >> 5;
            *(__half2*)&vd[(2 * dp) * VS + 2 * np] = __lows2half2(vxr[i], vyr[i]);
            *(__half2*)&vd[(2 * dp + 1) * VS + 2 * np] = __highs2half2(vxr[i], vyr[i]);
        }
    };

    // ---- issue first K/bias chunk, then pool agents while it's in flight ----
    issueKB(0, 0);
    loadVregs(0);

    // fused 8x8 mean pool: unit u = (agent a, 8-ch segment seg)
    for (int u = tid; u < AG * 8; u += 256) {
        int a = u >> 3, seg = u & 7;
        int py = a / 7, px = a % 7;
        float acc[8];
#pragma unroll
        for (int i = 0; i < 8; i++) acc[i] = 0.f;
#pragma unroll
        for (int dy = 0; dy < 8; dy++) {
            int nb = (py * 8 + dy) * Hpix + px * 8;
#pragma unroll
            for (int dx = 0; dx < 8; dx++) {
                uint4 raw = *(const uint4*)&g_qkvh[((size_t)(b * Nn + nb + dx)) * QKV + h * Dd + seg * 8];
                float2 f0 = __half22float2(*(__half2*)&raw.x);
                float2 f1 = __half22float2(*(__half2*)&raw.y);
                float2 f2 = __half22float2(*(__half2*)&raw.z);
                float2 f3 = __half22float2(*(__half2*)&raw.w);
                acc[0] += f0.x; acc[1] += f0.y;
                acc[2] += f1.x; acc[3] += f1.y;
                acc[4] += f2.x; acc[5] += f2.y;
                acc[6] += f3.x; acc[7] += f3.y;
            }
        }
        float* out = &g_agent[((size_t)b * AG + a) * Cc + h * Dd + seg * 8];
#pragma unroll
        for (int i = 0; i < 8; i++) acc[i] *= 0.015625f;
        *(float4*)out = make_float4(acc[0], acc[1], acc[2], acc[3]);
        *(float4*)(out + 4) = make_float4(acc[4], acc[5], acc[6], acc[7]);
        __half* aqp = &aq[a * FS + seg * 8];
#pragma unroll
        for (int i = 0; i < 4; i++) {
            __half2 hh = __floats2half2_rn(acc[2 * i] * 0.125f, acc[2 * i + 1] * 0.125f);
            *(__half2*)&aqp[2 * i] = hh;
        }
    }
    // zero-pad agent rows 49..63
    for (int f = tid; f < (64 - AG) * 64; f += 256) {
        int a = AG + (f >> 6), d = f & 63;
        aq[a * FS + d] = __float2half(0.f);
    }

    float m0 = -1e30f, m1 = -1e30f, l0 = 0.f, l1 = 0.f;
    float o[8][4];
#pragma unroll
    for (int j = 0; j < 8; j++)
#pragma unroll
        for (int t = 0; t < 4; t++) o[j][t] = 0.f;

    const int a0r = wm * 16 + g, a1r = a0r + 8;

    asm volatile("cp.async.wait_group 0;\n");
    stsV(0);
    __syncthreads();

    for (int c = 0; c < NCH; c++) {
        const int cur = c & 1, nxt = cur ^ 1;
        const int n0 = c * 128;
        if (c + 1 < NCH) {
            issueKB(nxt, (c + 1) * 128);
            loadVregs((c + 1) * 128);
        }
        const __half* ksb = (const __half*)(sm1 + S1_KS + cur * 18432);
        const __half* vsb = (const __half*)(sm1 + S1_VS + cur * 17408);
        const float* bib = (const float*)(sm1 + S1_BI + cur * 25872);

        float s[8][4];
#pragma unroll
        for (int j = 0; j < 8; j++)
#pragma unroll
            for (int t = 0; t < 4; t++) s[j][t] = 0.f;
#pragma unroll
        for (int t = 0; t < 4; t++) {
            int kk = t * 16 + 2 * cq;
            uint32_t A0 = *(const uint32_t*)&aq[(wm * 16 + g) * FS + kk];
            uint32_t A1 = *(const uint32_t*)&aq[(wm * 16 + g + 8) * FS + kk];
            uint32_t A2 = *(const uint32_t*)&aq[(wm * 16 + g) * FS + kk + 8];
            uint32_t A3 = *(const uint32_t*)&aq[(wm * 16 + g + 8) * FS + kk + 8];
#pragma unroll
            for (int j = 0; j < 8; j++) {
                int row = wn * 64 + j * 8 + g;
                uint32_t b0 = *(const uint32_t*)&ksb[row * FS + kk];
                uint32_t b1 = *(const uint32_t*)&ksb[row * FS + kk + 8];
                MMA16816(s[j], A0, A1, A2, A3, b0, b1);
            }
        }

        float cm0 = -1e30f, cm1 = -1e30f;
#pragma unroll
        for (int j = 0; j < 8; j++) {
            int nl = wn * 64 + j * 8 + 2 * cq;
            int n = n0 + nl;
            bool v0 = (n < Nn), v1 = (n + 1 < Nn);
            float ba00 = (a0r < AG) ? bib[a0r * 132 + nl] : 0.f;
            float ba01 = (a0r < AG) ? bib[a0r * 132 + nl + 1] : 0.f;
            float ba10 = (a1r < AG) ? bib[a1r * 132 + nl] : 0.f;
            float ba11 = (a1r < AG) ? bib[a1r * 132 + nl + 1] : 0.f;
            s[j][0] = v0 ? s[j][0] + ba00 : -1e30f;
            s[j][1] = v1 ? s[j][1] + ba01 : -1e30f;
            s[j][2] = v0 ? s[j][2] + ba10 : -1e30f;
            s[j][3] = v1 ? s[j][3] + ba11 : -1e30f;
            cm0 = fmaxf(cm0, fmaxf(s[j][0], s[j][1]));
            cm1 = fmaxf(cm1, fmaxf(s[j][2], s[j][3]));
        }
        cm0 = fmaxf(cm0, __shfl_xor_sync(0xffffffffu, cm0, 1));
        cm0 = fmaxf(cm0, __shfl_xor_sync(0xffffffffu, cm0, 2));
        cm1 = fmaxf(cm1, __shfl_xor_sync(0xffffffffu, cm1, 1));
        cm1 = fmaxf(cm1, __shfl_xor_sync(0xffffffffu, cm1, 2));

        float M0 = fmaxf(m0, cm0), M1 = fmaxf(m1, cm1);
        float r0 = __expf(m0 - M0), r1 = __expf(m1 - M1);
        float sum0 = 0.f, sum1 = 0.f;
#pragma unroll
        for (int j = 0; j < 8; j++) {
            s[j][0] = __expf(s[j][0] - M0);
            s[j][1] = __expf(s[j][1] - M0);
            s[j][2] = __expf(s[j][2] - M1);
            s[j][3] = __expf(s[j][3] - M1);
            sum0 += s[j][0] + s[j][1];
            sum1 += s[j][2] + s[j][3];
        }
        sum0 += __shfl_xor_sync(0xffffffffu, sum0, 1);
        sum0 += __shfl_xor_sync(0xffffffffu, sum0, 2);
        sum1 += __shfl_xor_sync(0xffffffffu, sum1, 1);
        sum1 += __shfl_xor_sync(0xffffffffu, sum1, 2);
        l0 = l0 * r0 + sum0;
        l1 = l1 * r1 + sum1;
        m0 = M0;
        m1 = M1;
#pragma unroll
        for (int j = 0; j < 8; j++) {
            o[j][0] *= r0; o[j][1] *= r0;
            o[j][2] *= r1; o[j][3] *= r1;
        }

        uint32_t pa[4][4];
#pragma unroll
        for (int t = 0; t < 4; t++) {
            __half2 h0 = __floats2half2_rn(s[2 * t][0], s[2 * t][1]);
            __half2 h1 = __floats2half2_rn(s[2 * t][2], s[2 * t][3]);
            __half2 h2 = __floats2half2_rn(s[2 * t + 1][0], s[2 * t + 1][1]);
            __half2 h3 = __floats2half2_rn(s[2 * t + 1][2], s[2 * t + 1][3]);
            pa[t][0] = *(uint32_t*)&h0;
            pa[t][1] = *(uint32_t*)&h1;
            pa[t][2] = *(uint32_t*)&h2;
            pa[t][3] = *(uint32_t*)&h3;
        }

#pragma unroll
        for (int t = 0; t < 4; t++) {
            int kk = wn * 64 + t * 16 + 2 * cq;
#pragma unroll
            for (int j = 0; j < 8; j++) {
                uint32_t b0 = *(const uint32_t*)&vsb[(j * 8 + g) * VS + kk];
                uint32_t b1 = *(const uint32_t*)&vsb[(j * 8 + g) * VS + kk + 8];
                MMA16816(o[j], pa[t][0], pa[t][1], pa[t][2], pa[t][3], b0, b1);
            }
        }

        if (c + 1 < NCH) {
            asm volatile("cp.async.wait_group 0;\n");
            stsV(nxt);
            __syncthreads();
        }
    }

    __syncthreads();
    float* p = mrg + ((size_t)(wm * 32 + lane)) * 36;
    if (wn == 1) {
#pragma unroll
        for (int j = 0; j < 8; j++) {
            p[4 * j] = o[j][0]; p[4 * j + 1] = o[j][1];
            p[4 * j + 2] = o[j][2]; p[4 * j + 3] = o[j][3];
        }
        p[32] = m0; p[33] = m1; p[34] = l0; p[35] = l1;
    }
    __syncthreads();
    if (wn == 0) {
        float pm0 = p[32], pm1 = p[33], pl0 = p[34], pl1 = p[35];
        float M0 = fmaxf(m0, pm0), M1 = fmaxf(m1, pm1);
        float ra0 = __expf(m0 - M0), rb0 = __expf(pm0 - M0);
        float ra1 = __expf(m1 - M1), rb1 = __expf(pm1 - M1);
        float i0 = 1.0f / (l0 * ra0 + pl0 * rb0);
        float i1 = 1.0f / (l1 * ra1 + pl1 * rb1);
#pragma unroll
        for (int j = 0; j < 8; j++) {
            int d = j * 8 + 2 * cq;
            if (a0r < AG) {
                float2 v = make_float2((o[j][0] * ra0 + p[4 * j] * rb0) * i0,
                                       (o[j][1] * ra0 + p[4 * j + 1] * rb0) * i0);
                *(float2*)&g_agentv[((size_t)bh * AG + a0r) * Dd + d] = v;
            }
            if (a1r < AG) {
                float2 v = make_float2((o[j][2] * ra1 + p[4 * j + 2] * rb1) * i1,
                                       (o[j][3] * ra1 + p[4 * j + 3] * rb1) * i1);
                *(float2*)&g_agentv[((size_t)bh * AG + a1r) * Dd + d] = v;
            }
        }
    }
}

// ---------------- stage 2 + fused dwc: out = softmax(q·a^T+b)@agent_v + conv(v) ---
#define S2S 72
#define S2_QH 0
#define S2_A4 18432
#define S2_AV 27648
#define S2_VN 36864
#define S2_WS 71712
#define S2_BS 74016
#define S2_SMEM 74272

__global__ __launch_bounds__(256) void stage2_mma(
    const float* __restrict__ dwc_w, const float* __restrict__ dwc_b)
{
    extern __shared__ char sm2[];
    __half* qh  = (__half*)(sm2 + S2_QH);
    __half* a4h = (__half*)(sm2 + S2_A4);
    __half* avh = (__half*)(sm2 + S2_AV);
    __half* vnb = (__half*)(sm2 + S2_VN);
    float* wsm  = (float*)(sm2 + S2_WS);
    float* bsm  = (float*)(sm2 + S2_BS);

    const int bh = blockIdx.y;
    const int b = bh / HEADS, h = bh % HEADS;
    const int n0 = blockIdx.x * 128;
    const int tid = threadIdx.x;
    const int wid = tid >> 5, lane = tid & 31;
    const int g = lane >> 2, cq = lane & 3;
    const int c0 = h * Dd;
    const int nlo = n0 - 57;

#pragma unroll
    for (int i = 0; i < 8; i++) {
        int idx = i * 256 + tid;
        if (idx < 242 * 8) {
            int r = idx >> 3, seg = idx & 7;
            int n = min(max(nlo + r, 0), Nn - 1);
            uint32_t p = (uint32_t)__cvta_generic_to_shared(vnb + r * S2S + seg * 8);
            CP_ASYNC16(p, &g_qkvh[((size_t)(b * Nn + n)) * QKV + 1024 + c0 + seg * 8]);
        }
    }
    asm volatile("cp.async.commit_group;\n");

#pragma unroll
    for (int i = 0; i < 4; i++) {
        int idx = i * 256 + tid;
        int r = idx >> 3, seg = idx & 7;
        int n = min(n0 + r, Nn - 1);
        *(uint4*)&qh[r * S2S + seg * 8] =
            *(const uint4*)&g_qkvh[((size_t)(b * Nn + n)) * QKV + c0 + seg * 8];
    }
#pragma unroll
    for (int i = 0; i < 16; i++) {
        int idx = i * 256 + tid;
        int a = idx >> 6, d = idx & 63;
        float av = (a < AG) ? g_agent[((size_t)b * AG + a) * Cc + c0 + d] * 0.125f : 0.f;
        float vv = (a < AG) ? g_agentv[((size_t)bh * AG + a) * Dd + d] : 0.f;
        a4h[a * S2S + d] = __float2half(av);
        avh[d * S2S + a] = __float2half(vv);
    }
    for (int i = tid; i < 9 * 64; i += 256) {
        int c = i & 63, tap = i >> 6;
        wsm[tap * 64 + c] = dwc_w[(c0 + c) * 9 + tap];
    }
    if (tid < 64) bsm[tid] = dwc_b[c0 + tid];
    __syncthreads();

    float s[8][4];
#pragma unroll
    for (int j = 0; j < 8; j++)
#pragma unroll
        for (int t = 0; t < 4; t++) s[j][t] = 0.f;

    const __half* qa = qh + (wid * 16) * S2S;
#pragma unroll
    for (int t = 0; t < 4; t++) {
        int k = t * 16 + 2 * cq;
        uint32_t a0 = *(const uint32_t*)&qa[g * S2S + k];
        uint32_t a1 = *(const uint32_t*)&qa[(g + 8) * S2S + k];
        uint32_t a2 = *(const uint32_t*)&qa[g * S2S + k + 8];
        uint32_t a3 = *(const uint32_t*)&qa[(g + 8) * S2S + k + 8];
#pragma unroll
        for (int j = 0; j < 8; j++) {
            uint32_t b0 = *(const uint32_t*)&a4h[(j * 8 + g) * S2S + k];
            uint32_t b1 = *(const uint32_t*)&a4h[(j * 8 + g) * S2S + k + 8];
            MMA16816(s[j], a0, a1, a2, a3, b0, b1);
        }
    }

    const int r0 = n0 + wid * 16 + g;
    const int r1 = r0 + 8;
    float m0 = -1e30f, m1 = -1e30f;
#pragma unroll
    for (int j = 0; j < 8; j++) {
        int a = 8 * j + 2 * cq;
        if (a < AG) {
            float b00 = (r0 < Nn) ? g_bias_qa[((size_t)h * Nn + r0) * AG + a] : 0.f;
            float b10 = (r1 < Nn) ? g_bias_qa[((size_t)h * Nn + r1) * AG + a] : 0.f;
            s[j][0] += b00;
            s[j][2] += b10;
            if (a + 1 < AG) {
                float b01 = (r0 < Nn) ? g_bias_qa[((size_t)h * Nn + r0) * AG + a + 1] : 0.f;
                float b11 = (r1 < Nn) ? g_bias_qa[((size_t)h * Nn + r1) * AG + a + 1] : 0.f;
                s[j][1] += b01;
                s[j][3] += b11;
            } else {
                s[j][1] = -1e30f;
                s[j][3] = -1e30f;
            }
        } else {
            s[j][0] = -1e30f; s[j][1] = -1e30f;
            s[j][2] = -1e30f; s[j][3] = -1e30f;
        }
        m0 = fmaxf(m0, fmaxf(s[j][0], s[j][1]));
        m1 = fmaxf(m1, fmaxf(s[j][2], s[j][3]));
    }
    m0 = fmaxf(m0, __shfl_xor_sync(0xffffffffu, m0, 1));
    m0 = fmaxf(m0, __shfl_xor_sync(0xffffffffu, m0, 2));
    m1 = fmaxf(m1, __shfl_xor_sync(0xffffffffu, m1, 1));
    m1 = fmaxf(m1, __shfl_xor_sync(0xffffffffu, m1, 2));

    float sum0 = 0.f, sum1 = 0.f;
#pragma unroll
    for (int j = 0; j < 8; j++) {
        s[j][0] = __expf(s[j][0] - m0);
        s[j][1] = __expf(s[j][1] - m0);
        s[j][2] = __expf(s[j][2] - m1);
        s[j][3] = __expf(s[j][3] - m1);
        sum0 += s[j][0] + s[j][1];
        sum1 += s[j][2] + s[j][3];
    }
    sum0 += __shfl_xor_sync(0xffffffffu, sum0, 1);
    sum0 += __shfl_xor_sync(0xffffffffu, sum0, 2);
    sum1 += __shfl_xor_sync(0xffffffffu, sum1, 1);
    sum1 += __shfl_xor_sync(0xffffffffu, sum1, 2);
    const float inv0 = 1.0f / sum0, inv1 = 1.0f / sum1;

    uint32_t pa[4][4];
#pragma unroll
    for (int t = 0; t < 4; t++) {
        __half2 h0 = __floats2half2_rn(s[2 * t][0], s[2 * t][1]);
        __half2 h1 = __floats2half2_rn(s[2 * t][2], s[2 * t][3]);
        __half2 h2 = __floats2half2_rn(s[2 * t + 1][0], s[2 * t + 1][1]);
        __half2 h3 = __floats2half2_rn(s[2 * t + 1][2], s[2 * t + 1][3]);
        pa[t][0] = *(uint32_t*)&h0;
        pa[t][1] = *(uint32_t*)&h1;
        pa[t][2] = *(uint32_t*)&h2;
        pa[t][3] = *(uint32_t*)&h3;
    }

    float o[8][4];
#pragma unroll
    for (int j = 0; j < 8; j++)
#pragma unroll
        for (int t = 0; t < 4; t++) o[j][t] = 0.f;
#pragma unroll
    for (int t = 0; t < 4; t++) {
        int k = t * 16 + 2 * cq;
#pragma unroll
        for (int j = 0; j < 8; j++) {
            uint32_t b0 = *(const uint32_t*)&avh[(j * 8 + g) * S2S + k];
            uint32_t b1 = *(const uint32_t*)&avh[(j * 8 + g) * S2S + k + 8];
            MMA16816(o[j], pa[t][0], pa[t][1], pa[t][2], pa[t][3], b0, b1);
        }
    }

    asm volatile("cp.async.wait_group 0;\n");
    __syncthreads();

#pragma unroll
    for (int ri = 0; ri < 2; ri++) {
        int r = ri ? r1 : r0;
        if (r >= Nn) continue;
        float inv = ri ? inv1 : inv0;
        int y = r / Hpix, x = r % Hpix;
        float da[8][2];
#pragma unroll
        for (int j = 0; j < 8; j++) {
            int dl = 8 * j + 2 * cq;
            da[j][0] = bsm[dl];
            da[j][1] = bsm[dl + 1];
        }
#pragma unroll
        for (int tap = 0; tap < 9; tap++) {
            int dy = tap / 3 - 1, dx = tap % 3 - 1;
            int yy = y + dy, xx = x + dx;
            if (yy < 0 || yy >= Hpix || xx < 0 || xx >= Hpix) continue;
            int vrow = r + dy * Hpix + dx - nlo;
#pragma unroll
            for (int j = 0; j < 8; j++) {
                int dl = 8 * j + 2 * cq;
                float2 f = __half22float2(*(const __half2*)&vnb[vrow * S2S + dl]);
                da[j][0] = fmaf(f.x, wsm[tap * 64 + dl], da[j][0]);
                da[j][1] = fmaf(f.y, wsm[tap * 64 + dl + 1], da[j][1]);
            }
        }
#pragma unroll
        for (int j = 0; j < 8; j++) {
            int dl = 8 * j + 2 * cq;
            __half2 v = __floats2half2_rn(o[j][2 * ri] * inv + da[j][0],
                                          o[j][2 * ri + 1] * inv + da[j][1]);
            *(__half2*)&g_acch[((size_t)(b * Nn + r)) * Cc + c0 + dl] = v;
        }
    }
}

// ---------------- launch ----------------
extern "C" void kernel_launch(void* const* d_in, const int* in_sizes, int n_in,
                              void* d_out, int out_size)
{
    const float* x      = (const float*)d_in[0];
    const float* q_w    = (const float*)d_in[1];
    const float* kv_w   = (const float*)d_in[2];
    const float* proj_w = (const float*)d_in[3];
    const float* proj_b = (const float*)d_in[4];
    const float* dwc_w  = (const float*)d_in[5];
    const float* dwc_b  = (const float*)d_in[6];
    const float* an_b   = (const float*)d_in[7];
    const float* na_b   = (const float*)d_in[8];
    const float* ah     = (const float*)d_in[9];
    const float* aw     = (const float*)d_in[10];
    const float* ha     = (const float*)d_in[11];
    const float* wa     = (const float*)d_in[12];

    __half *qkvp, *xhp, *acchp, *wtp;
    cudaGetSymbolAddress((void**)&qkvp, g_qkvh);
    cudaGetSymbolAddress((void**)&xhp, g_xh);
    cudaGetSymbolAddress((void**)&acchp, g_acch);
    cudaGetSymbolAddress((void**)&wtp, g_wTh);

    cudaFuncSetAttribute(gemm_h, cudaFuncAttributeMaxDynamicSharedMemorySize, GT_SMEM);
    cudaFuncSetAttribute(stage1_mma, cudaFuncAttributeMaxDynamicSharedMemorySize, S1_SMEM);
    cudaFuncSetAttribute(stage2_mma, cudaFuncAttributeMaxDynamicSharedMemorySize, S2_SMEM);

    const int M = Bn * Nn;  // 50176

    wtrans_all<<<dim3(2048 / 32, 512 / 32), 256>>>(q_w, kv_w, proj_w, wtp);
    xconv_kernel<<<(int)(((size_t)M * Cc / 8) / 256), 256>>>(x, xhp);
    gemm_h<<<dim3(QKV / 128, M / 128), 256, GT_SMEM>>>(xhp, wtp, nullptr, qkvp,
                                                        M, Cc, QKV, nullptr);
    bias_all<<<(2 * T_AK) / 256, 256>>>(an_b, ah, aw, na_b, ha, wa);
    stage1_mma<<<Bn * HEADS, 256, S1_SMEM>>>();
    stage2_mma<<<dim3(25, Bn * HEADS), 256, S2_SMEM>>>(dwc_w, dwc_b);
    gemm_h<<<dim3(Cc / 128, M / 128), 256, GT_SMEM>>>(acchp, wtp + WT_PROJ, (float*)d_out,
                                                       nullptr, M, Cc, Cc, proj_b);
}

// round 15
// speedup vs baseline: 1.4073x; 1.0104x over previous
#include <cuda_runtime.h>
#include <cuda_fp16.h>
#include <cstdint>
#include <math.h>

#define Bn 16
#define Nn 3136
#define Cc 512
#define Hpix 56
#define HEADS 8
#define Dd 64
#define AG 49
#define QKV 1536

// ---------------- scratch (device globals; no allocation allowed) ----------------
__device__ __half g_qkvh[(size_t)Bn * Nn * QKV];       // fp16: q[0,512) k[512,1024) v[1024,1536)
__device__ float g_agent[(size_t)Bn * AG * Cc];        // (b,a,c) written by stage1
__device__ float g_bias_ak[(size_t)HEADS * AG * Nn + 128]; // (h,a,n) +pad for cp.async tail
__device__ float g_bias_qa[(size_t)HEADS * Nn * AG];   // (h,n,a)
__device__ float g_agentv[(size_t)Bn * HEADS * AG * Dd];
__device__ __half g_xh[(size_t)Bn * Nn * Cc];          // x in fp16
__device__ __half g_acch[(size_t)Bn * Nn * Cc];        // attn out + dwc (fp16)
// transposed fp16 weights: [qT|kT|vT] rows 0..1535, projT rows 1536..2047; K-major K=512
__device__ __half g_wTh[(size_t)2048 * 512];
#define WT_PROJ (1536 * 512)

#define MMA16816(acc, a0, a1, a2, a3, b0, b1)                                   \
    asm volatile(                                                               \
        "mma.sync.aligned.m16n8k16.row.col.f32.f16.f16.f32 "                    \
        "{%0,%1,%2,%3}, {%4,%5,%6,%7}, {%8,%9}, {%0,%1,%2,%3};"                 \
        : "+f"(acc[0]), "+f"(acc[1]), "+f"(acc[2]), "+f"(acc[3])                \
        : "r"(a0), "r"(a1), "r"(a2), "r"(a3), "r"(b0), "r"(b1))

#define LDSM_X4(r0, r1, r2, r3, addr)                                           \
    asm volatile("ldmatrix.sync.aligned.m8n8.x4.shared.b16 {%0,%1,%2,%3}, [%4];" \
                 : "=r"(r0), "=r"(r1), "=r"(r2), "=r"(r3) : "r"(addr))

#define CP_ASYNC16(dst, src)                                                    \
    asm volatile("cp.async.cg.shared.global [%0], [%1], 16;\n" :: "r"(dst), "l"(src))

// ---------------- fp16 tensor-core GEMM: C = A[M,K] @ Bt[Nc,K]^T (+bias) ----------
// BM=BN=128 BK=64, 8 warps, 3-stage cp.async, 2 CTAs/SM.  (PINNED config)
#define GAS 72
#define GBUF (128 * GAS)
#define GSTAGES 3
#define GT_SMEM (GSTAGES * 2 * GBUF * 2)   // 110592 bytes

__global__ __launch_bounds__(256, 2) void gemm_h(
    const __half* __restrict__ A, const __half* __restrict__ Bt,
    float* __restrict__ Cout, __half* __restrict__ CoutH,
    int M, int K, int Nc, const float* __restrict__ bias)
{
    extern __shared__ __half smh[];
    __half* smA = smh;
    __half* smB = smh + GSTAGES * GBUF;
    const int tid = threadIdx.x;
    const int wid = tid >> 5, lane = tid & 31;
    const int wm = wid & 3, wn = wid >> 2;
    const int g = lane >> 2, cq = lane & 3;
    const int bm = blockIdx.y * 128, bn = blockIdx.x * 128;

    const uint32_t smA_u = (uint32_t)__cvta_generic_to_shared(smA);
    const uint32_t smB_u = (uint32_t)__cvta_generic_to_shared(smB);
    const uint32_t aOff = (wm * 32 + (lane & 15)) * GAS * 2 + (lane >> 4) * 16;
    const uint32_t bOff = (wn * 64 + (lane & 15)) * GAS * 2 + (lane >> 4) * 16;

    float acc[2][8][4];
#pragma unroll
    for (int i = 0; i < 2; i++)
#pragma unroll
        for (int j = 0; j < 8; j++)
#pragma unroll
            for (int t = 0; t < 4; t++) acc[i][j][t] = 0.f;

    auto loadAB = [&](int s, int kc) {
        const __half* ga = A + (size_t)bm * K + kc * 64;
        const __half* gb = Bt + (size_t)bn * K + kc * 64;
        __half* da = smA + s * GBUF;
        __half* db = smB + s * GBUF;
#pragma unroll
        for (int i = 0; i < 4; i++) {
            int idx = i * 256 + tid;
            int row = idx >> 3, seg = idx & 7;
            uint32_t pa = (uint32_t)__cvta_generic_to_shared(da + row * GAS + seg * 8);
            uint32_t pb = (uint32_t)__cvta_generic_to_shared(db + row * GAS + seg * 8);
            CP_ASYNC16(pa, ga + (size_t)row * K + seg * 8);
            CP_ASYNC16(pb, gb + (size_t)row * K + seg * 8);
        }
        asm volatile("cp.async.commit_group;\n");
    };

    const int KT = K / 64;   // 8
    loadAB(0, 0);
    loadAB(1, 1);
    loadAB(2, 2);

    for (int c = 0; c < KT; c++) {
        int s = c % GSTAGES;
        if (c + 2 < KT)      asm volatile("cp.async.wait_group 2;\n");
        else if (c + 1 < KT) asm volatile("cp.async.wait_group 1;\n");
        else                 asm volatile("cp.async.wait_group 0;\n");
        __syncthreads();
        const uint32_t aP = smA_u + s * (GBUF * 2) + aOff;
        const uint32_t bP = smB_u + s * (GBUF * 2) + bOff;
#pragma unroll
        for (int ks = 0; ks < 4; ks++) {
            const uint32_t kb = ks * 32;
            uint32_t a[2][4];
            LDSM_X4(a[0][0], a[0][1], a[0][2], a[0][3], aP + kb);
            LDSM_X4(a[1][0], a[1][1], a[1][2], a[1][3], aP + 16 * GAS * 2 + kb);
#pragma unroll
            for (int jj = 0; jj < 4; jj++) {
                uint32_t rb0, rb1, rb2, rb3;
                LDSM_X4(rb0, rb1, rb2, rb3, bP + jj * (16 * GAS * 2) + kb);
#pragma unroll
                for (int i = 0; i < 2; i++) {
                    MMA16816(acc[i][2 * jj],     a[i][0], a[i][1], a[i][2], a[i][3], rb0, rb2);
                    MMA16816(acc[i][2 * jj + 1], a[i][0], a[i][1], a[i][2], a[i][3], rb1, rb3);
                }
            }
        }
        __syncthreads();
        if (c + GSTAGES < KT) loadAB(s, c + GSTAGES);
    }

#pragma unroll
    for (int j = 0; j < 8; j++) {
        int col = bn + wn * 64 + j * 8 + 2 * cq;
        float bx = 0.f, by = 0.f;
        if (bias) { bx = bias[col]; by = bias[col + 1]; }
#pragma unroll
        for (int i = 0; i < 2; i++) {
            int r0 = bm + wm * 32 + i * 16 + g;
            if (CoutH) {
                __half2 h0 = __floats2half2_rn(acc[i][j][0] + bx, acc[i][j][1] + by);
                __half2 h1 = __floats2half2_rn(acc[i][j][2] + bx, acc[i][j][3] + by);
                *(__half2*)&CoutH[(size_t)r0 * Nc + col] = h0;
                *(__half2*)&CoutH[(size_t)(r0 + 8) * Nc + col] = h1;
            } else {
                *(float2*)&Cout[(size_t)r0 * Nc + col] =
                    make_float2(acc[i][j][0] + bx, acc[i][j][1] + by);
                *(float2*)&Cout[(size_t)(r0 + 8) * Nc + col] =
                    make_float2(acc[i][j][2] + bx, acc[i][j][3] + by);
            }
        }
    }
}

// ---------------- merged prep: xconv (blocks < 12544) + wtrans (rest) -------------
#define XB 12544   // (Bn*Nn*Cc/8)/256
__global__ __launch_bounds__(256) void prep_kernel(
    const float* __restrict__ x, __half* __restrict__ xh,
    const float* __restrict__ qw, const float* __restrict__ kvw,
    const float* __restrict__ pw, __half* __restrict__ Wt)
{
    __shared__ float t[32][33];
    if (blockIdx.x < XB) {
        size_t i = (size_t)blockIdx.x * 256 + threadIdx.x;
        float4 v0 = ((const float4*)x)[2 * i];
        float4 v1 = ((const float4*)x)[2 * i + 1];
        __half2 h0 = __floats2half2_rn(v0.x, v0.y);
        __half2 h1 = __floats2half2_rn(v0.z, v0.w);
        __half2 h2 = __floats2half2_rn(v1.x, v1.y);
        __half2 h3 = __floats2half2_rn(v1.z, v1.w);
        uint4 o;
        o.x = *(uint32_t*)&h0;
        o.y = *(uint32_t*)&h1;
        o.z = *(uint32_t*)&h2;
        o.w = *(uint32_t*)&h3;
        ((uint4*)xh)[i] = o;
    } else {
        int bid = blockIdx.x - XB;
        int n0 = (bid & 63) * 32, k0 = (bid >> 6) * 32;
        const float* W;
        int Nc, col0;
        if (n0 < 512)       { W = qw;  Nc = 512;  col0 = n0; }
        else if (n0 < 1536) { W = kvw; Nc = 1024; col0 = n0 - 512; }
        else                { W = pw;  Nc = 512;  col0 = n0 - 1536; }
        int tx = threadIdx.x & 31, ty = threadIdx.x >> 5;
#pragma unroll
        for (int i = 0; i < 32; i += 8)
            t[ty + i][tx] = W[(size_t)(k0 + ty + i) * Nc + col0 + tx];
        __syncthreads();
#pragma unroll
        for (int i = 0; i < 32; i += 8)
            Wt[(size_t)(n0 + ty + i) * 512 + k0 + tx] = __float2half(t[tx][ty + i]);
    }
}

// ---------------- bias tables, hoisted-weight version ----------------
// ak: thread = (haa, 8-n row segment): y-taps computed once.
// qa: thread = (h, n, 7-agent group): full taps computed once, reused 7x.
#define AKU (HEADS * AG * (Nn / 8))   // 153664
#define QAU (HEADS * Nn * 7)          // 175616
#define BIAS_BLOCKS ((AKU + QAU + 255) / 256)

__global__ __launch_bounds__(256) void bias_all(
    const float* __restrict__ an, const float* __restrict__ ah, const float* __restrict__ aw,
    const float* __restrict__ na, const float* __restrict__ ha, const float* __restrict__ wa)
{
    int u = blockIdx.x * 256 + threadIdx.x;
    if (u < AKU) {
        int haa = u / (Nn / 8);
        int ng = u % (Nn / 8);
        int n0 = ng * 8;
        int y = n0 / Hpix, x0 = n0 % Hpix;      // 8-blocks never cross rows (56%8==0)
        float sy = (y + 0.5f) * 0.125f - 0.5f;
        int y0f = (int)floorf(sy);
        float wy = sy - (float)y0f;
        int y0 = min(6, max(0, y0f));
        int y1 = min(6, max(0, y0f + 1));
        const float* tt = an + haa * 49;
        float cst = ah[haa] + aw[haa];
        float out[8];
#pragma unroll
        for (int i = 0; i < 8; i++) {
            int x = x0 + i;
            float sx = (x + 0.5f) * 0.125f - 0.5f;
            int x0f = (int)floorf(sx);
            float wx = sx - (float)x0f;
            int xa = min(6, max(0, x0f));
            int xb = min(6, max(0, x0f + 1));
            float v00 = tt[y0 * 7 + xa], v01 = tt[y0 * 7 + xb];
            float v10 = tt[y1 * 7 + xa], v11 = tt[y1 * 7 + xb];
            float top = v00 + wx * (v01 - v00);
            float bot = v10 + wx * (v11 - v10);
            out[i] = top + wy * (bot - top) + cst;
        }
        float* dst = &g_bias_ak[(size_t)haa * Nn + n0];
        *(float4*)dst = make_float4(out[0], out[1], out[2], out[3]);
        *(float4*)(dst + 4) = make_float4(out[4], out[5], out[6], out[7]);
    } else if (u < AKU + QAU) {
        int u2 = u - AKU;
        int h = u2 / (Nn * 7);
        int rem = u2 % (Nn * 7);
        int n = rem / 7;
        int gi = rem % 7;
        int y = n / Hpix, x = n % Hpix;
        float sy = (y + 0.5f) * 0.125f - 0.5f;
        float sx = (x + 0.5f) * 0.125f - 0.5f;
        int y0f = (int)floorf(sy);
        int x0f = (int)floorf(sx);
        float wy = sy - (float)y0f;
        float wx = sx - (float)x0f;
        int y0 = min(6, max(0, y0f));
        int y1 = min(6, max(0, y0f + 1));
        int xa = min(6, max(0, x0f));
        int xb = min(6, max(0, x0f + 1));
        int a0 = gi * 7;
        float* dst = &g_bias_qa[((size_t)h * Nn + n) * AG + a0];
#pragma unroll
        for (int k = 0; k < 7; k++) {
            int haa = h * AG + a0 + k;
            const float* tt = na + haa * 49;
            float v00 = tt[y0 * 7 + xa], v01 = tt[y0 * 7 + xb];
            float v10 = tt[y1 * 7 + xa], v11 = tt[y1 * 7 + xb];
            float top = v00 + wx * (v01 - v00);
            float bot = v10 + wx * (v11 - v10);
            dst[k] = top + wy * (bot - top) + ha[haa] + wa[haa];
        }
    }
}

// ---------------- stage 1 (flash, tensor cores) + fused agent pooling -------------
#define FS 72
#define VS 136
#define NCH 25
#define S1_AQ 0
#define S1_KS 9216
#define S1_VS 46080
#define S1_BI 80896
#define S1_SMEM 132640

__global__ __launch_bounds__(256) void stage1_mma()
{
    extern __shared__ char sm1[];
    __half* aq = (__half*)(sm1 + S1_AQ);
    float* mrg = (float*)(sm1 + S1_KS);

    const int bh = blockIdx.x;
    const int b = bh / HEADS, h = bh % HEADS;
    const int tid = threadIdx.x;
    const int wid = tid >> 5, lane = tid & 31;
    const int wm = wid & 3, wn = wid >> 2;
    const int g = lane >> 2, cq = lane & 3;

    auto issueKB = [&](int buf, int n0) {
        char* kdst = sm1 + S1_KS + buf * 18432;
#pragma unroll
        for (int i = 0; i < 4; i++) {
            int idx = i * 256 + tid;
            int r = idx >> 3, seg = idx & 7;
            int n = min(n0 + r, Nn - 1);
            uint32_t p = (uint32_t)__cvta_generic_to_shared(kdst + (r * FS + seg * 8) * 2);
            CP_ASYNC16(p, &g_qkvh[((size_t)(b * Nn + n)) * QKV + 512 + h * Dd + seg * 8]);
        }
        char* bdst = sm1 + S1_BI + buf * 25872;
        for (int f = tid; f < AG * 32; f += 256) {
            int a = f >> 5, seg = f & 31;
            uint32_t p = (uint32_t)__cvta_generic_to_shared(bdst + (a * 132 + seg * 4) * 4);
            CP_ASYNC16(p, &g_bias_ak[((size_t)(h * AG + a)) * Nn + n0 + seg * 4]);
        }
        asm volatile("cp.async.commit_group;\n");
    };

    __half2 vxr[8], vyr[8];
    auto loadVregs = [&](int n0) {
#pragma unroll
        for (int i = 0; i < 8; i++) {
            int idx = i * 256 + tid;
            int dp = idx & 31, np = idx >> 5;
            int na = min(n0 + 2 * np, Nn - 1);
            int nb = min(n0 + 2 * np + 1, Nn - 1);
            vxr[i] = *(const __half2*)&g_qkvh[((size_t)(b * Nn + na)) * QKV + 1024 + h * Dd + dp * 2];
            vyr[i] = *(const __half2*)&g_qkvh[((size_t)(b * Nn + nb)) * QKV + 1024 + h * Dd + dp * 2];
        }
    };
    auto stsV = [&](int buf) {
        __half* vd = (__half*)(sm1 + S1_VS + buf * 17408);
#pragma unroll
        for (int i = 0; i < 8; i++) {
            int idx = i * 256 + tid;
            int dp = idx & 31, np = idx >> 5;
            *(__half2*)&vd[(2 * dp) * VS + 2 * np] = __lows2half2(vxr[i], vyr[i]);
            *(__half2*)&vd[(2 * dp + 1) * VS + 2 * np] = __highs2half2(vxr[i], vyr[i]);
        }
    };

    // ---- issue first K/bias chunk, then pool agents while it's in flight ----
    issueKB(0, 0);
    loadVregs(0);

    // fused 8x8 mean pool: unit u = (agent a, 8-ch segment seg)
    for (int u = tid; u < AG * 8; u += 256) {
        int a = u >> 3, seg = u & 7;
        int py = a / 7, px = a % 7;
        float acc[8];
#pragma unroll
        for (int i = 0; i < 8; i++) acc[i] = 0.f;
#pragma unroll
        for (int dy = 0; dy < 8; dy++) {
            int nb = (py * 8 + dy) * Hpix + px * 8;
#pragma unroll
            for (int dx = 0; dx < 8; dx++) {
                uint4 raw = *(const uint4*)&g_qkvh[((size_t)(b * Nn + nb + dx)) * QKV + h * Dd + seg * 8];
                float2 f0 = __half22float2(*(__half2*)&raw.x);
                float2 f1 = __half22float2(*(__half2*)&raw.y);
                float2 f2 = __half22float2(*(__half2*)&raw.z);
                float2 f3 = __half22float2(*(__half2*)&raw.w);
                acc[0] += f0.x; acc[1] += f0.y;
                acc[2] += f1.x; acc[3] += f1.y;
                acc[4] += f2.x; acc[5] += f2.y;
                acc[6] += f3.x; acc[7] += f3.y;
            }
        }
        float* out = &g_agent[((size_t)b * AG + a) * Cc + h * Dd + seg * 8];
#pragma unroll
        for (int i = 0; i < 8; i++) acc[i] *= 0.015625f;
        *(float4*)out = make_float4(acc[0], acc[1], acc[2], acc[3]);
        *(float4*)(out + 4) = make_float4(acc[4], acc[5], acc[6], acc[7]);
        __half* aqp = &aq[a * FS + seg * 8];
#pragma unroll
        for (int i = 0; i < 4; i++) {
            __half2 hh = __floats2half2_rn(acc[2 * i] * 0.125f, acc[2 * i + 1] * 0.125f);
            *(__half2*)&aqp[2 * i] = hh;
        }
    }
    // zero-pad agent rows 49..63
    for (int f = tid; f < (64 - AG) * 64; f += 256) {
        int a = AG + (f >> 6), d = f & 63;
        aq[a * FS + d] = __float2half(0.f);
    }

    float m0 = -1e30f, m1 = -1e30f, l0 = 0.f, l1 = 0.f;
    float o[8][4];
#pragma unroll
    for (int j = 0; j < 8; j++)
#pragma unroll
        for (int t = 0; t < 4; t++) o[j][t] = 0.f;

    const int a0r = wm * 16 + g, a1r = a0r + 8;

    asm volatile("cp.async.wait_group 0;\n");
    stsV(0);
    __syncthreads();

    for (int c = 0; c < NCH; c++) {
        const int cur = c & 1, nxt = cur ^ 1;
        const int n0 = c * 128;
        if (c + 1 < NCH) {
            issueKB(nxt, (c + 1) * 128);
            loadVregs((c + 1) * 128);
        }
        const __half* ksb = (const __half*)(sm1 + S1_KS + cur * 18432);
        const __half* vsb = (const __half*)(sm1 + S1_VS + cur * 17408);
        const float* bib = (const float*)(sm1 + S1_BI + cur * 25872);

        float s[8][4];
#pragma unroll
        for (int j = 0; j < 8; j++)
#pragma unroll
            for (int t = 0; t < 4; t++) s[j][t] = 0.f;
#pragma unroll
        for (int t = 0; t < 4; t++) {
            int kk = t * 16 + 2 * cq;
            uint32_t A0 = *(const uint32_t*)&aq[(wm * 16 + g) * FS + kk];
            uint32_t A1 = *(const uint32_t*)&aq[(wm * 16 + g + 8) * FS + kk];
            uint32_t A2 = *(const uint32_t*)&aq[(wm * 16 + g) * FS + kk + 8];
            uint32_t A3 = *(const uint32_t*)&aq[(wm * 16 + g + 8) * FS + kk + 8];
#pragma unroll
            for (int j = 0; j < 8; j++) {
                int row = wn * 64 + j * 8 + g;
                uint32_t b0 = *(const uint32_t*)&ksb[row * FS + kk];
                uint32_t b1 = *(const uint32_t*)&ksb[row * FS + kk + 8];
                MMA16816(s[j], A0, A1, A2, A3, b0, b1);
            }
        }

        float cm0 = -1e30f, cm1 = -1e30f;
#pragma unroll
        for (int j = 0; j < 8; j++) {
            int nl = wn * 64 + j * 8 + 2 * cq;
            int n = n0 + nl;
            bool v0 = (n < Nn), v1 = (n + 1 < Nn);
            float ba00 = (a0r < AG) ? bib[a0r * 132 + nl] : 0.f;
            float ba01 = (a0r < AG) ? bib[a0r * 132 + nl + 1] : 0.f;
            float ba10 = (a1r < AG) ? bib[a1r * 132 + nl] : 0.f;
            float ba11 = (a1r < AG) ? bib[a1r * 132 + nl + 1] : 0.f;
            s[j][0] = v0 ? s[j][0] + ba00 : -1e30f;
            s[j][1] = v1 ? s[j][1] + ba01 : -1e30f;
            s[j][2] = v0 ? s[j][2] + ba10 : -1e30f;
            s[j][3] = v1 ? s[j][3] + ba11 : -1e30f;
            cm0 = fmaxf(cm0, fmaxf(s[j][0], s[j][1]));
            cm1 = fmaxf(cm1, fmaxf(s[j][2], s[j][3]));
        }
        cm0 = fmaxf(cm0, __shfl_xor_sync(0xffffffffu, cm0, 1));
        cm0 = fmaxf(cm0, __shfl_xor_sync(0xffffffffu, cm0, 2));
        cm1 = fmaxf(cm1, __shfl_xor_sync(0xffffffffu, cm1, 1));
        cm1 = fmaxf(cm1, __shfl_xor_sync(0xffffffffu, cm1, 2));

        float M0 = fmaxf(m0, cm0), M1 = fmaxf(m1, cm1);
        float r0 = __expf(m0 - M0), r1 = __expf(m1 - M1);
        float sum0 = 0.f, sum1 = 0.f;
#pragma unroll
        for (int j = 0; j < 8; j++) {
            s[j][0] = __expf(s[j][0] - M0);
            s[j][1] = __expf(s[j][1] - M0);
            s[j][2] = __expf(s[j][2] - M1);
            s[j][3] = __expf(s[j][3] - M1);
            sum0 += s[j][0] + s[j][1];
            sum1 += s[j][2] + s[j][3];
        }
        sum0 += __shfl_xor_sync(0xffffffffu, sum0, 1);
        sum0 += __shfl_xor_sync(0xffffffffu, sum0, 2);
        sum1 += __shfl_xor_sync(0xffffffffu, sum1, 1);
        sum1 += __shfl_xor_sync(0xffffffffu, sum1, 2);
        l0 = l0 * r0 + sum0;
        l1 = l1 * r1 + sum1;
        m0 = M0;
        m1 = M1;
#pragma unroll
        for (int j = 0; j < 8; j++) {
            o[j][0] *= r0; o[j][1] *= r0;
            o[j][2] *= r1; o[j][3] *= r1;
        }

        uint32_t pa[4][4];
#pragma unroll
        for (int t = 0; t < 4; t++) {
            __half2 h0 = __floats2half2_rn(s[2 * t][0], s[2 * t][1]);
            __half2 h1 = __floats2half2_rn(s[2 * t][2], s[2 * t][3]);
            __half2 h2 = __floats2half2_rn(s[2 * t + 1][0], s[2 * t + 1][1]);
            __half2 h3 = __floats2half2_rn(s[2 * t + 1][2], s[2 * t + 1][3]);
            pa[t][0] = *(uint32_t*)&h0;
            pa[t][1] = *(uint32_t*)&h1;
            pa[t][2] = *(uint32_t*)&h2;
            pa[t][3] = *(uint32_t*)&h3;
        }

#pragma unroll
        for (int t = 0; t < 4; t++) {
            int kk = wn * 64 + t * 16 + 2 * cq;
#pragma unroll
            for (int j = 0; j < 8; j++) {
                uint32_t b0 = *(const uint32_t*)&vsb[(j * 8 + g) * VS + kk];
                uint32_t b1 = *(const uint32_t*)&vsb[(j * 8 + g) * VS + kk + 8];
                MMA16816(o[j], pa[t][0], pa[t][1], pa[t][2], pa[t][3], b0, b1);
            }
        }

        if (c + 1 < NCH) {
            asm volatile("cp.async.wait_group 0;\n");
            stsV(nxt);
            __syncthreads();
        }
    }

    __syncthreads();
    float* p = mrg + ((size_t)(wm * 32 + lane)) * 36;
    if (wn == 1) {
#pragma unroll
        for (int j = 0; j < 8; j++) {
            p[4 * j] = o[j][0]; p[4 * j + 1] = o[j][1];
            p[4 * j + 2] = o[j][2]; p[4 * j + 3] = o[j][3];
        }
        p[32] = m0; p[33] = m1; p[34] = l0; p[35] = l1;
    }
    __syncthreads();
    if (wn == 0) {
        float pm0 = p[32], pm1 = p[33], pl0 = p[34], pl1 = p[35];
        float M0 = fmaxf(m0, pm0), M1 = fmaxf(m1, pm1);
        float ra0 = __expf(m0 - M0), rb0 = __expf(pm0 - M0);
        float ra1 = __expf(m1 - M1), rb1 = __expf(pm1 - M1);
        float i0 = 1.0f / (l0 * ra0 + pl0 * rb0);
        float i1 = 1.0f / (l1 * ra1 + pl1 * rb1);
#pragma unroll
        for (int j = 0; j < 8; j++) {
            int d = j * 8 + 2 * cq;
            if (a0r < AG) {
                float2 v = make_float2((o[j][0] * ra0 + p[4 * j] * rb0) * i0,
                                       (o[j][1] * ra0 + p[4 * j + 1] * rb0) * i0);
                *(float2*)&g_agentv[((size_t)bh * AG + a0r) * Dd + d] = v;
            }
            if (a1r < AG) {
                float2 v = make_float2((o[j][2] * ra1 + p[4 * j + 2] * rb1) * i1,
                                       (o[j][3] * ra1 + p[4 * j + 3] * rb1) * i1);
                *(float2*)&g_agentv[((size_t)bh * AG + a1r) * Dd + d] = v;
            }
        }
    }
}

// ---------------- stage 2 + fused dwc: out = softmax(q·a^T+b)@agent_v + conv(v) ---
#define S2S 72
#define S2_QH 0
#define S2_A4 18432
#define S2_AV 27648
#define S2_VN 36864
#define S2_WS 71712
#define S2_BS 74016
#define S2_SMEM 74272

__global__ __launch_bounds__(256) void stage2_mma(
    const float* __restrict__ dwc_w, const float* __restrict__ dwc_b)
{
    extern __shared__ char sm2[];
    __half* qh  = (__half*)(sm2 + S2_QH);
    __half* a4h = (__half*)(sm2 + S2_A4);
    __half* avh = (__half*)(sm2 + S2_AV);
    __half* vnb = (__half*)(sm2 + S2_VN);
    float* wsm  = (float*)(sm2 + S2_WS);
    float* bsm  = (float*)(sm2 + S2_BS);

    const int bh = blockIdx.y;
    const int b = bh / HEADS, h = bh % HEADS;
    const int n0 = blockIdx.x * 128;
    const int tid = threadIdx.x;
    const int wid = tid >> 5, lane = tid & 31;
    const int g = lane >> 2, cq = lane & 3;
    const int c0 = h * Dd;
    const int nlo = n0 - 57;

#pragma unroll
    for (int i = 0; i < 8; i++) {
        int idx = i * 256 + tid;
        if (idx < 242 * 8) {
            int r = idx >> 3, seg = idx & 7;
            int n = min(max(nlo + r, 0), Nn - 1);
            uint32_t p = (uint32_t)__cvta_generic_to_shared(vnb + r * S2S + seg * 8);
            CP_ASYNC16(p, &g_qkvh[((size_t)(b * Nn + n)) * QKV + 1024 + c0 + seg * 8]);
        }
    }
    asm volatile("cp.async.commit_group;\n");

#pragma unroll
    for (int i = 0; i < 4; i++) {
        int idx = i * 256 + tid;
        int r = idx >> 3, seg = idx & 7;
        int n = min(n0 + r, Nn - 1);
        *(uint4*)&qh[r * S2S + seg * 8] =
            *(const uint4*)&g_qkvh[((size_t)(b * Nn + n)) * QKV + c0 + seg * 8];
    }
#pragma unroll
    for (int i = 0; i < 16; i++) {
        int idx = i * 256 + tid;
        int a = idx >> 6, d = idx & 63;
        float av = (a < AG) ? g_agent[((size_t)b * AG + a) * Cc + c0 + d] * 0.125f : 0.f;
        float vv = (a < AG) ? g_agentv[((size_t)bh * AG + a) * Dd + d] : 0.f;
        a4h[a * S2S + d] = __float2half(av);
        avh[d * S2S + a] = __float2half(vv);
    }
    for (int i = tid; i < 9 * 64; i += 256) {
        int c = i & 63, tap = i >> 6;
        wsm[tap * 64 + c] = dwc_w[(c0 + c) * 9 + tap];
    }
    if (tid < 64) bsm[tid] = dwc_b[c0 + tid];
    __syncthreads();

    float s[8][4];
#pragma unroll
    for (int j = 0; j < 8; j++)
#pragma unroll
        for (int t = 0; t < 4; t++) s[j][t] = 0.f;

    const __half* qa = qh + (wid * 16) * S2S;
#pragma unroll
    for (int t = 0; t < 4; t++) {
        int k = t * 16 + 2 * cq;
        uint32_t a0 = *(const uint32_t*)&qa[g * S2S + k];
        uint32_t a1 = *(const uint32_t*)&qa[(g + 8) * S2S + k];
        uint32_t a2 = *(const uint32_t*)&qa[g * S2S + k + 8];
        uint32_t a3 = *(const uint32_t*)&qa[(g + 8) * S2S + k + 8];
#pragma unroll
        for (int j = 0; j < 8; j++) {
            uint32_t b0 = *(const uint32_t*)&a4h[(j * 8 + g) * S2S + k];
            uint32_t b1 = *(const uint32_t*)&a4h[(j * 8 + g) * S2S + k + 8];
            MMA16816(s[j], a0, a1, a2, a3, b0, b1);
        }
    }

    const int r0 = n0 + wid * 16 + g;
    const int r1 = r0 + 8;
    float m0 = -1e30f, m1 = -1e30f;
#pragma unroll
    for (int j = 0; j < 8; j++) {
        int a = 8 * j + 2 * cq;
        if (a < AG) {
            float b00 = (r0 < Nn) ? g_bias_qa[((size_t)h * Nn + r0) * AG + a] : 0.f;
            float b10 = (r1 < Nn) ? g_bias_qa[((size_t)h * Nn + r1) * AG + a] : 0.f;
            s[j][0] += b00;
            s[j][2] += b10;
            if (a + 1 < AG) {
                float b01 = (r0 < Nn) ? g_bias_qa[((size_t)h * Nn + r0) * AG + a + 1] : 0.f;
                float b11 = (r1 < Nn) ? g_bias_qa[((size_t)h * Nn + r1) * AG + a + 1] : 0.f;
                s[j][1] += b01;
                s[j][3] += b11;
            } else {
                s[j][1] = -1e30f;
                s[j][3] = -1e30f;
            }
        } else {
            s[j][0] = -1e30f; s[j][1] = -1e30f;
            s[j][2] = -1e30f; s[j][3] = -1e30f;
        }
        m0 = fmaxf(m0, fmaxf(s[j][0], s[j][1]));
        m1 = fmaxf(m1, fmaxf(s[j][2], s[j][3]));
    }
    m0 = fmaxf(m0, __shfl_xor_sync(0xffffffffu, m0, 1));
    m0 = fmaxf(m0, __shfl_xor_sync(0xffffffffu, m0, 2));
    m1 = fmaxf(m1, __shfl_xor_sync(0xffffffffu, m1, 1));
    m1 = fmaxf(m1, __shfl_xor_sync(0xffffffffu, m1, 2));

    float sum0 = 0.f, sum1 = 0.f;
#pragma unroll
    for (int j = 0; j < 8; j++) {
        s[j][0] = __expf(s[j][0] - m0);
        s[j][1] = __expf(s[j][1] - m0);
        s[j][2] = __expf(s[j][2] - m1);
        s[j][3] = __expf(s[j][3] - m1);
        sum0 += s[j][0] + s[j][1];
        sum1 += s[j][2] + s[j][3];
    }
    sum0 += __shfl_xor_sync(0xffffffffu, sum0, 1);
    sum0 += __shfl_xor_sync(0xffffffffu, sum0, 2);
    sum1 += __shfl_xor_sync(0xffffffffu, sum1, 1);
    sum1 += __shfl_xor_sync(0xffffffffu, sum1, 2);
    const float inv0 = 1.0f / sum0, inv1 = 1.0f / sum1;

    uint32_t pa[4][4];
#pragma unroll
    for (int t = 0; t < 4; t++) {
        __half2 h0 = __floats2half2_rn(s[2 * t][0], s[2 * t][1]);
        __half2 h1 = __floats2half2_rn(s[2 * t][2], s[2 * t][3]);
        __half2 h2 = __floats2half2_rn(s[2 * t + 1][0], s[2 * t + 1][1]);
        __half2 h3 = __floats2half2_rn(s[2 * t + 1][2], s[2 * t + 1][3]);
        pa[t][0] = *(uint32_t*)&h0;
        pa[t][1] = *(uint32_t*)&h1;
        pa[t][2] = *(uint32_t*)&h2;
        pa[t][3] = *(uint32_t*)&h3;
    }

    float o[8][4];
#pragma unroll
    for (int j = 0; j < 8; j++)
#pragma unroll
        for (int t = 0; t < 4; t++) o[j][t] = 0.f;
#pragma unroll
    for (int t = 0; t < 4; t++) {
        int k = t * 16 + 2 * cq;
#pragma unroll
        for (int j = 0; j < 8; j++) {
            uint32_t b0 = *(const uint32_t*)&avh[(j * 8 + g) * S2S + k];
            uint32_t b1 = *(const uint32_t*)&avh[(j * 8 + g) * S2S + k + 8];
            MMA16816(o[j], pa[t][0], pa[t][1], pa[t][2], pa[t][3], b0, b1);
        }
    }

    asm volatile("cp.async.wait_group 0;\n");
    __syncthreads();

#pragma unroll
    for (int ri = 0; ri < 2; ri++) {
        int r = ri ? r1 : r0;
        if (r >= Nn) continue;
        float inv = ri ? inv1 : inv0;
        int y = r / Hpix, x = r % Hpix;
        float da[8][2];
#pragma unroll
        for (int j = 0; j < 8; j++) {
            int dl = 8 * j + 2 * cq;
            da[j][0] = bsm[dl];
            da[j][1] = bsm[dl + 1];
        }
#pragma unroll
        for (int tap = 0; tap < 9; tap++) {
            int dy = tap / 3 - 1, dx = tap % 3 - 1;
            int yy = y + dy, xx = x + dx;
            if (yy < 0 || yy >= Hpix || xx < 0 || xx >= Hpix) continue;
            int vrow = r + dy * Hpix + dx - nlo;
#pragma unroll
            for (int j = 0; j < 8; j++) {
                int dl = 8 * j + 2 * cq;
                float2 f = __half22float2(*(const __half2*)&vnb[vrow * S2S + dl]);
                da[j][0] = fmaf(f.x, wsm[tap * 64 + dl], da[j][0]);
                da[j][1] = fmaf(f.y, wsm[tap * 64 + dl + 1], da[j][1]);
            }
        }
#pragma unroll
        for (int j = 0; j < 8; j++) {
            int dl = 8 * j + 2 * cq;
            __half2 v = __floats2half2_rn(o[j][2 * ri] * inv + da[j][0],
                                          o[j][2 * ri + 1] * inv + da[j][1]);
            *(__half2*)&g_acch[((size_t)(b * Nn + r)) * Cc + c0 + dl] = v;
        }
    }
}

// ---------------- launch ----------------
extern "C" void kernel_launch(void* const* d_in, const int* in_sizes, int n_in,
                              void* d_out, int out_size)
{
    const float* x      = (const float*)d_in[0];
    const float* q_w    = (const float*)d_in[1];
    const float* kv_w   = (const float*)d_in[2];
    const float* proj_w = (const float*)d_in[3];
    const float* proj_b = (const float*)d_in[4];
    const float* dwc_w  = (const float*)d_in[5];
    const float* dwc_b  = (const float*)d_in[6];
    const float* an_b   = (const float*)d_in[7];
    const float* na_b   = (const float*)d_in[8];
    const float* ah     = (const float*)d_in[9];
    const float* aw     = (const float*)d_in[10];
    const float* ha     = (const float*)d_in[11];
    const float* wa     = (const float*)d_in[12];

    __half *qkvp, *xhp, *acchp, *wtp;
    cudaGetSymbolAddress((void**)&qkvp, g_qkvh);
    cudaGetSymbolAddress((void**)&xhp, g_xh);
    cudaGetSymbolAddress((void**)&acchp, g_acch);
    cudaGetSymbolAddress((void**)&wtp, g_wTh);

    cudaFuncSetAttribute(gemm_h, cudaFuncAttributeMaxDynamicSharedMemorySize, GT_SMEM);
    cudaFuncSetAttribute(stage1_mma, cudaFuncAttributeMaxDynamicSharedMemorySize, S1_SMEM);
    cudaFuncSetAttribute(stage2_mma, cudaFuncAttributeMaxDynamicSharedMemorySize, S2_SMEM);

    const int M = Bn * Nn;  // 50176

    prep_kernel<<<XB + 1024, 256>>>(x, xhp, q_w, kv_w, proj_w, wtp);
    gemm_h<<<dim3(QKV / 128, M / 128), 256, GT_SMEM>>>(xhp, wtp, nullptr, qkvp,
                                                        M, Cc, QKV, nullptr);
    bias_all<<<BIAS_BLOCKS, 256>>>(an_b, ah, aw, na_b, ha, wa);
    stage1_mma<<<Bn * HEADS, 256, S1_SMEM>>>();
    stage2_mma<<<dim3(25, Bn * HEADS), 256, S2_SMEM>>>(dwc_w, dwc_b);
    gemm_h<<<dim3(Cc / 128, M / 128), 256, GT_SMEM>>>(acchp, wtp + WT_PROJ, (float*)d_out,
                                                       nullptr, M, Cc, Cc, proj_b);
}